// round 11
// baseline (speedup 1.0000x reference)
#include <cuda_runtime.h>
#include <cuda_bf16.h>
#include <cstdint>

#define B_ 2
#define H_ 8
#define S_ 2048
#define D_ 64
#define BH_ (B_ * H_)
#define OUT_OFF ((size_t)B_ * H_ * S_ * D_)   // output tensor first, then weights
#define KBLK 32                                // av chunks (64 wide)
#define QBLK 16                                // logits k-blocks (128 wide)

__device__ float  g_bias_lut[H_ * 2 * S_];
__device__ float  g_sums[BH_ * S_ * QBLK];    // per (row, 128-kblock) partial expsum
// packed bf16 hi/lo planes
__device__ unsigned g_Qh[BH_ * S_ * 32];
__device__ unsigned g_Ql[BH_ * S_ * 32];
__device__ unsigned g_Kh[BH_ * S_ * 32];
__device__ unsigned g_Kl[BH_ * S_ * 32];
__device__ unsigned g_Vth[BH_ * KBLK * 64 * 32];   // [bh][chunk][d][kpair]
__device__ unsigned g_Vtl[BH_ * KBLK * 64 * 32];

// ---- helpers ----------------------------------------------------------------
__device__ __forceinline__ void split_pack(float x0, float x1, unsigned& hi, unsigned& lo) {
    __nv_bfloat162 h = __floats2bfloat162_rn(x0, x1);
    float f0 = __bfloat162float(__low2bfloat16(h));
    float f1 = __bfloat162float(__high2bfloat16(h));
    __nv_bfloat162 l = __floats2bfloat162_rn(x0 - f0, x1 - f1);
    hi = *reinterpret_cast<unsigned*>(&h);
    lo = *reinterpret_cast<unsigned*>(&l);
}
__device__ __forceinline__ void mma16(float* d, const unsigned* a, const unsigned* b) {
    asm("mma.sync.aligned.m16n8k16.row.col.f32.bf16.bf16.f32 "
        "{%0,%1,%2,%3},{%4,%5,%6,%7},{%8,%9},{%0,%1,%2,%3};"
        : "+f"(d[0]), "+f"(d[1]), "+f"(d[2]), "+f"(d[3])
        : "r"(a[0]), "r"(a[1]), "r"(a[2]), "r"(a[3]), "r"(b[0]), "r"(b[1]));
}
__device__ __forceinline__ void ldm4(unsigned* r, unsigned addr) {
    asm volatile("ldmatrix.sync.aligned.m8n8.x4.shared.b16 {%0,%1,%2,%3}, [%4];"
        : "=r"(r[0]), "=r"(r[1]), "=r"(r[2]), "=r"(r[3]) : "r"(addr));
}
__device__ __forceinline__ void cpa16(unsigned dst, const void* src) {
    asm volatile("cp.async.cg.shared.global [%0], [%1], 16;" :: "r"(dst), "l"(src));
}
__device__ __forceinline__ void cpa_commit() { asm volatile("cp.async.commit_group;"); }
__device__ __forceinline__ void cpa_wait0()  { asm volatile("cp.async.wait_group 0;"); }
__device__ __forceinline__ float ex2f(float x) {
    float r; asm("ex2.approx.f32 %0, %1;" : "=f"(r) : "f"(x)); return r;
}
#define LOG2E 1.4426950408889634f
__device__ __forceinline__ float exp_nomax(float x) {
    return ex2f(fmaxf(x * LOG2E, -126.0f));
}

// ---------------------------------------------------------------------------
// Kernel 0: T5 bias LUT (exact integer bucket thresholds)
// ---------------------------------------------------------------------------
__global__ void bias_lut_kernel(const float* __restrict__ bias_table) {
    int idx = blockIdx.x * blockDim.x + threadIdx.x;
    if (idx >= H_ * 2 * S_) return;
    int h   = idx >> 12;
    int r   = idx & 4095;
    int rel = r - 2048;
    int bucket = (rel > 0) ? 16 : 0;
    int a = rel < 0 ? -rel : rel;
    int add;
    if      (a <  8) add = a;
    else if (a < 12) add = 8;
    else if (a < 16) add = 9;
    else if (a < 23) add = 10;
    else if (a < 32) add = 11;
    else if (a < 46) add = 12;
    else if (a < 64) add = 13;
    else if (a < 91) add = 14;
    else             add = 15;
    g_bias_lut[idx] = bias_table[(bucket + add) * H_ + h];
}

// ---------------------------------------------------------------------------
// Kernel 0a: Q,K -> packed row-major bf16 hi/lo planes
// ---------------------------------------------------------------------------
__global__ __launch_bounds__(256) void qk_prep_kernel(
    const float* __restrict__ Q, const float* __restrict__ K)
{
    int idx = blockIdx.x * 256 + threadIdx.x;
    const float2 q2 = *(const float2*)&Q[2 * (size_t)idx];
    const float2 k2 = *(const float2*)&K[2 * (size_t)idx];
    unsigned hi, lo;
    split_pack(q2.x, q2.y, hi, lo);
    g_Qh[idx] = hi; g_Ql[idx] = lo;
    split_pack(k2.x, k2.y, hi, lo);
    g_Kh[idx] = hi; g_Kl[idx] = lo;
}

// ---------------------------------------------------------------------------
// Kernel 0b: V -> packed transposed bf16 hi/lo planes [bh][chunk][d][kp]
// ---------------------------------------------------------------------------
__global__ __launch_bounds__(256) void v_prep_kernel(const float* __restrict__ V)
{
    __shared__ float Vs[64 * 68];
    int c  = blockIdx.x;
    int bh = blockIdx.y;
    int t  = threadIdx.x;
    const float* Vp = V + (size_t)bh * S_ * D_ + (size_t)c * 64 * D_;
    #pragma unroll
    for (int i = 0; i < 4; i++) {
        int idx = t + i * 256;
        int k = idx >> 4, d4 = idx & 15;
        *(float4*)&Vs[k * 68 + d4 * 4] = *(const float4*)&Vp[(size_t)k * D_ + d4 * 4];
    }
    __syncthreads();
    unsigned base = ((unsigned)bh * KBLK + c) * 64 * 32;
    #pragma unroll
    for (int i = 0; i < 8; i++) {
        int idx = t + i * 256;
        int d = idx >> 5, kp = idx & 31;
        unsigned hh, ll;
        split_pack(Vs[(2 * kp) * 68 + d], Vs[(2 * kp + 1) * 68 + d], hh, ll);
        g_Vth[base + d * 32 + kp] = hh;
        g_Vtl[base + d * 32 + kp] = ll;
    }
}

// ---------------------------------------------------------------------------
// Kernel 1: writes expW = exp(QK^T/8 + bias + mask*-1e9) + partial row sums.
// Tile 128(q) x 128(k), 8 warps (4m x 2n). N split into two 64-col halves
// processed sequentially (32 live accumulators), launch_bounds(256,3).
// ---------------------------------------------------------------------------
#define QSTR 36
#define L_QH 0
#define L_QL (128 * QSTR)
#define L_KH (2 * 128 * QSTR)
#define L_KL (3 * 128 * QSTR)
#define L_LUT (4 * 128 * QSTR)
#define L_SMEM ((L_LUT + 288) * 4)

__global__ __launch_bounds__(256, 3) void logits_kernel(
    const int* __restrict__ mask, float* __restrict__ out)
{
    extern __shared__ unsigned smu[];
    float* sLut = (float*)(smu + L_LUT);

    int bh = blockIdx.z;
    int q0 = blockIdx.y * 128;
    int k0 = blockIdx.x * 128;
    int b  = bh >> 3;
    int h  = bh & 7;

    int t = threadIdx.x;
    int w = t >> 5, l = t & 31, g = l >> 2, tg = l & 3;
    int wm = w & 3, wn = w >> 2;

    int lbase = k0 - q0 + 2048 - 128;
    for (int i = t; i < 288; i += 256) {
        int ix = lbase + i;
        ix = ix < 0 ? 0 : (ix > 4095 ? 4095 : ix);
        sLut[i] = g_bias_lut[h * 4096 + ix];
    }

    unsigned sbase = (unsigned)__cvta_generic_to_shared(smu);
    unsigned qrow = (unsigned)bh * S_ + q0;
    unsigned krow = (unsigned)bh * S_ + k0;
    #pragma unroll
    for (int i = 0; i < 4; i++) {
        int idx = t + i * 256;
        int r = idx >> 3, sg = idx & 7;
        cpa16(sbase + (L_QH + r * QSTR + sg * 4) * 4, &g_Qh[(qrow + r) * 32 + sg * 4]);
        cpa16(sbase + (L_QL + r * QSTR + sg * 4) * 4, &g_Ql[(qrow + r) * 32 + sg * 4]);
        cpa16(sbase + (L_KH + r * QSTR + sg * 4) * 4, &g_Kh[(krow + r) * 32 + sg * 4]);
        cpa16(sbase + (L_KL + r * QSTR + sg * 4) * 4, &g_Kl[(krow + r) * 32 + sg * 4]);
    }
    cpa_commit(); cpa_wait0();
    __syncthreads();

    int lq = l & 7, lh8 = (l >> 3) & 1, lc = (l >> 4);
    int qd = l >> 3;
    unsigned aoff = ((wm * 32 + lh8 * 8 + lq) * QSTR + lc * 4) * 4;
    unsigned boff = ((wn * 64 + (qd >> 1) * 8 + lq) * QSTR + (qd & 1) * 4) * 4;

    float* wbase = out + OUT_OFF + (size_t)bh * S_ * S_;
    float rsum[4] = {0.f, 0.f, 0.f, 0.f};

    #pragma unroll
    for (int half = 0; half < 2; half++) {
        float C[2][4][4] = {};

        #pragma unroll
        for (int ks = 0; ks < 4; ks++) {
            unsigned ah[2][4], al[2][4];
            #pragma unroll
            for (int mt = 0; mt < 2; mt++) {
                ldm4(ah[mt], sbase + L_QH * 4 + aoff + mt * (16 * QSTR * 4) + ks * 32);
                ldm4(al[mt], sbase + L_QL * 4 + aoff + mt * (16 * QSTR * 4) + ks * 32);
            }
            #pragma unroll
            for (int ntp = 0; ntp < 2; ntp++) {
                unsigned bhf[4], blf[4];
                ldm4(bhf, sbase + L_KH * 4 + boff + (half * 2 + ntp) * (16 * QSTR * 4) + ks * 32);
                ldm4(blf, sbase + L_KL * 4 + boff + (half * 2 + ntp) * (16 * QSTR * 4) + ks * 32);
                #pragma unroll
                for (int mt = 0; mt < 2; mt++) {
                    mma16(C[mt][2 * ntp],     ah[mt], bhf);
                    mma16(C[mt][2 * ntp],     ah[mt], blf);
                    mma16(C[mt][2 * ntp],     al[mt], bhf);
                    mma16(C[mt][2 * ntp + 1], ah[mt], bhf + 2);
                    mma16(C[mt][2 * ntp + 1], ah[mt], blf + 2);
                    mma16(C[mt][2 * ntp + 1], al[mt], bhf + 2);
                }
            }
        }

        // epilogue for this 32-col half of the warp's N range
        #pragma unroll
        for (int nt = 0; nt < 4; nt++) {
            int kcol = k0 + wn * 64 + half * 32 + nt * 8 + 2 * tg;
            int jc = (kcol - k0) + 128;
            float mv0 = -1e9f * (float)mask[b * S_ + kcol];
            float mv1 = -1e9f * (float)mask[b * S_ + kcol + 1];
            #pragma unroll
            for (int mt = 0; mt < 2; mt++) {
                int q = q0 + wm * 32 + mt * 16 + g;
                int jq = jc - (q - q0);
                float e0 = exp_nomax(fmaf(C[mt][nt][0], 0.125f, sLut[jq]     + mv0));
                float e1 = exp_nomax(fmaf(C[mt][nt][1], 0.125f, sLut[jq + 1] + mv1));
                *(float2*)&wbase[(size_t)q * S_ + kcol] = make_float2(e0, e1);
                int jq2 = jq - 8;
                float e2 = exp_nomax(fmaf(C[mt][nt][2], 0.125f, sLut[jq2]     + mv0));
                float e3 = exp_nomax(fmaf(C[mt][nt][3], 0.125f, sLut[jq2 + 1] + mv1));
                *(float2*)&wbase[(size_t)(q + 8) * S_ + kcol] = make_float2(e2, e3);
                rsum[mt * 2]     += e0 + e1;
                rsum[mt * 2 + 1] += e2 + e3;
            }
        }
    }

    #pragma unroll
    for (int ri = 0; ri < 4; ri++) {
        rsum[ri] += __shfl_xor_sync(0xffffffffu, rsum[ri], 1);
        rsum[ri] += __shfl_xor_sync(0xffffffffu, rsum[ri], 2);
    }
    __syncthreads();

    float* sSum = (float*)smu;   // [128][2]
    if (tg == 0) {
        #pragma unroll
        for (int ri = 0; ri < 4; ri++) {
            int rl = wm * 32 + (ri >> 1) * 16 + (ri & 1) * 8 + g;
            sSum[rl * 2 + wn] = rsum[ri];
        }
    }
    __syncthreads();
    if (t < 128)
        g_sums[((size_t)bh * S_ + q0 + t) * QBLK + blockIdx.x] = sSum[t * 2] + sSum[t * 2 + 1];
}

// ---------------------------------------------------------------------------
// Kernel 2: av. Reads expW (cp.async double-buffered), scales by invS,
// writes normalized weights once, P@V via ldmatrix + bf16 3-term mma.
// ---------------------------------------------------------------------------
#define PSTR 36
#define RAWSTR 68
#define OFF_RAW   0
#define OFF_PH    (2 * 64 * RAWSTR)
#define OFF_PL    (OFF_PH + 64 * PSTR)
#define OFF_VH    (OFF_PL + 64 * PSTR)
#define OFF_VL    (OFF_VH + 2 * 64 * PSTR)
#define OFF_ST    (OFF_VL + 2 * 64 * PSTR)
#define AV_SMEM   ((OFF_ST + 64) * 4)

__global__ __launch_bounds__(256, 2) void av_kernel(
    float* __restrict__ W, float* __restrict__ out)
{
    extern __shared__ unsigned smu[];
    float*    rawW = (float*)smu;
    unsigned* Ph   = smu + OFF_PH;
    unsigned* Pl   = smu + OFF_PL;
    float*    sI   = (float*)(smu + OFF_ST);

    int bh = blockIdx.y;
    int q0 = blockIdx.x * 64;

    float* Wp = W + OUT_OFF + (size_t)bh * S_ * S_;

    int t = threadIdx.x;
    int w = t >> 5, l = t & 31, g = l >> 2, tg = l & 3;
    int wm = w & 3, wn = w >> 2;

    unsigned sbase = (unsigned)__cvta_generic_to_shared(smu);

    int lq = l & 7, lh8 = (l >> 3) & 1, lc = (l >> 4);
    int qd = l >> 3;
    unsigned aoff = ((wm * 16 + lh8 * 8 + lq) * PSTR + lc * 4) * 4;
    unsigned boff = ((wn * 32 + (qd >> 1) * 8 + lq) * PSTR + (qd & 1) * 4) * 4;

    if (t < 64) {
        const float* ps = &g_sums[((size_t)bh * S_ + q0 + t) * QBLK];
        float s = 0.f;
        #pragma unroll
        for (int i = 0; i < QBLK; i++) s += ps[i];
        sI[t] = 1.0f / s;
    }

    // prefetch chunk 0 into stage 0
    {
        #pragma unroll
        for (int i = 0; i < 4; i++) {
            int idx = t + i * 256;
            int r = idx >> 4, c4 = idx & 15;
            cpa16(sbase + (OFF_RAW + r * RAWSTR + c4 * 4) * 4,
                  &Wp[(size_t)(q0 + r) * S_ + c4 * 4]);
        }
        unsigned vb = (unsigned)bh * KBLK * 64 * 32;
        #pragma unroll
        for (int i = 0; i < 2; i++) {
            int idx = t + i * 256;
            int d = idx >> 3, sg = idx & 7;
            cpa16(sbase + (OFF_VH + d * PSTR + sg * 4) * 4, &g_Vth[vb + d * 32 + sg * 4]);
            cpa16(sbase + (OFF_VL + d * PSTR + sg * 4) * 4, &g_Vtl[vb + d * 32 + sg * 4]);
        }
        cpa_commit();
    }

    float C[4][4] = {};

    for (int kci = 0; kci < KBLK; kci++) {
        int kc = kci * 64;
        int st = kci & 1;
        cpa_wait0();
        __syncthreads();

        if (kci + 1 < KBLK) {
            int s = (kci + 1) & 1;
            #pragma unroll
            for (int i = 0; i < 4; i++) {
                int idx = t + i * 256;
                int r = idx >> 4, c4 = idx & 15;
                cpa16(sbase + (OFF_RAW + s * 64 * RAWSTR + r * RAWSTR + c4 * 4) * 4,
                      &Wp[(size_t)(q0 + r) * S_ + kc + 64 + c4 * 4]);
            }
            unsigned vb = ((unsigned)bh * KBLK + kci + 1) * 64 * 32;
            #pragma unroll
            for (int i = 0; i < 2; i++) {
                int idx = t + i * 256;
                int d = idx >> 3, sg = idx & 7;
                cpa16(sbase + (OFF_VH + s * 64 * PSTR + d * PSTR + sg * 4) * 4,
                      &g_Vth[vb + d * 32 + sg * 4]);
                cpa16(sbase + (OFF_VL + s * 64 * PSTR + d * PSTR + sg * 4) * 4,
                      &g_Vtl[vb + d * 32 + sg * 4]);
            }
            cpa_commit();
        }

        // fill P: p = expW * invS; write normalized; pack
        #pragma unroll
        for (int i = 0; i < 4; i++) {
            int idx = t + i * 256;
            int q = idx >> 4, f4 = idx & 15;
            float4 wv = *(const float4*)&rawW[st * 64 * RAWSTR + q * RAWSTR + f4 * 4];
            float I = sI[q];
            float p0 = wv.x * I, p1 = wv.y * I, p2 = wv.z * I, p3 = wv.w * I;
            *(float4*)&Wp[(size_t)(q0 + q) * S_ + kc + f4 * 4] = make_float4(p0, p1, p2, p3);
            unsigned h0, l0, h1, l1;
            split_pack(p0, p1, h0, l0);
            split_pack(p2, p3, h1, l1);
            *(uint2*)&Ph[q * PSTR + 2 * f4] = make_uint2(h0, h1);
            *(uint2*)&Pl[q * PSTR + 2 * f4] = make_uint2(l0, l1);
        }
        __syncthreads();

        unsigned vhb = (OFF_VH + st * 64 * PSTR) * 4;
        unsigned vlb = (OFF_VL + st * 64 * PSTR) * 4;
        #pragma unroll
        for (int ks = 0; ks < 4; ks++) {
            unsigned ah[4], al[4];
            ldm4(ah, sbase + OFF_PH * 4 + aoff + ks * 32);
            ldm4(al, sbase + OFF_PL * 4 + aoff + ks * 32);
            #pragma unroll
            for (int ntp = 0; ntp < 2; ntp++) {
                unsigned bhf[4], blf[4];
                ldm4(bhf, sbase + vhb + boff + ntp * (16 * PSTR * 4) + ks * 32);
                ldm4(blf, sbase + vlb + boff + ntp * (16 * PSTR * 4) + ks * 32);
                mma16(C[2 * ntp],     ah, bhf);
                mma16(C[2 * ntp],     ah, blf);
                mma16(C[2 * ntp],     al, bhf);
                mma16(C[2 * ntp + 1], ah, bhf + 2);
                mma16(C[2 * ntp + 1], ah, blf + 2);
                mma16(C[2 * ntp + 1], al, bhf + 2);
            }
        }
        __syncthreads();
    }

    #pragma unroll
    for (int nt = 0; nt < 4; nt++) {
        int d = wn * 32 + nt * 8 + 2 * tg;
        int q = q0 + wm * 16 + g;
        *(float2*)&out[((size_t)bh * S_ + q) * D_ + d]     = make_float2(C[nt][0], C[nt][1]);
        *(float2*)&out[((size_t)bh * S_ + q + 8) * D_ + d] = make_float2(C[nt][2], C[nt][3]);
    }
}

// ---------------------------------------------------------------------------
extern "C" void kernel_launch(void* const* d_in, const int* in_sizes, int n_in,
                              void* d_out, int out_size)
{
    const float* Q    = (const float*)d_in[0];
    const float* K    = (const float*)d_in[1];
    const float* V    = (const float*)d_in[2];
    const int*   mask = (const int*)d_in[3];
    const float* bt   = (const float*)d_in[4];
    float* out = (float*)d_out;

    cudaFuncSetAttribute(logits_kernel, cudaFuncAttributeMaxDynamicSharedMemorySize, L_SMEM);
    cudaFuncSetAttribute(av_kernel,     cudaFuncAttributeMaxDynamicSharedMemorySize, AV_SMEM);

    bias_lut_kernel<<<32, 1024>>>(bt);
    qk_prep_kernel<<<BH_ * S_ * 32 / 256, 256>>>(Q, K);
    dim3 gv(KBLK, BH_);
    v_prep_kernel<<<gv, 256>>>(V);

    dim3 g1(S_ / 128, S_ / 128, BH_);   // (16, 16, 16)
    logits_kernel<<<g1, 256, L_SMEM>>>(mask, out);

    dim3 g2(S_ / 64, BH_);              // (32, 16)
    av_kernel<<<g2, 256, AV_SMEM>>>(out, out);
}

// round 12
// speedup vs baseline: 1.0105x; 1.0105x over previous
#include <cuda_runtime.h>
#include <cuda_bf16.h>
#include <cstdint>

#define B_ 2
#define H_ 8
#define S_ 2048
#define D_ 64
#define BH_ (B_ * H_)
#define OUT_OFF ((size_t)B_ * H_ * S_ * D_)   // output tensor first, then weights
#define KBLK 32                                // av chunks (64 wide)
#define QBLK 16                                // logits k-blocks (128 wide)

__device__ float  g_bias_lut[H_ * 2 * S_];
__device__ float  g_sums[BH_ * S_ * QBLK];    // per (row, 128-kblock) partial expsum
// packed bf16 hi/lo planes
__device__ unsigned g_Qh[BH_ * S_ * 32];
__device__ unsigned g_Ql[BH_ * S_ * 32];
__device__ unsigned g_Kh[BH_ * S_ * 32];
__device__ unsigned g_Kl[BH_ * S_ * 32];
__device__ unsigned g_Vth[BH_ * KBLK * 64 * 32];   // [bh][chunk][d][kpair]
__device__ unsigned g_Vtl[BH_ * KBLK * 64 * 32];
// unnormalized expW planes: [bh][q][kpair]  (bf16x2, 67MB each)
__device__ unsigned g_Eh[(size_t)BH_ * S_ * 1024];
__device__ unsigned g_El[(size_t)BH_ * S_ * 1024];

// ---- helpers ----------------------------------------------------------------
__device__ __forceinline__ void split_pack(float x0, float x1, unsigned& hi, unsigned& lo) {
    __nv_bfloat162 h = __floats2bfloat162_rn(x0, x1);
    float f0 = __bfloat162float(__low2bfloat16(h));
    float f1 = __bfloat162float(__high2bfloat16(h));
    __nv_bfloat162 l = __floats2bfloat162_rn(x0 - f0, x1 - f1);
    hi = *reinterpret_cast<unsigned*>(&h);
    lo = *reinterpret_cast<unsigned*>(&l);
}
__device__ __forceinline__ void mma16(float* d, const unsigned* a, const unsigned* b) {
    asm("mma.sync.aligned.m16n8k16.row.col.f32.bf16.bf16.f32 "
        "{%0,%1,%2,%3},{%4,%5,%6,%7},{%8,%9},{%0,%1,%2,%3};"
        : "+f"(d[0]), "+f"(d[1]), "+f"(d[2]), "+f"(d[3])
        : "r"(a[0]), "r"(a[1]), "r"(a[2]), "r"(a[3]), "r"(b[0]), "r"(b[1]));
}
__device__ __forceinline__ void ldm4(unsigned* r, unsigned addr) {
    asm volatile("ldmatrix.sync.aligned.m8n8.x4.shared.b16 {%0,%1,%2,%3}, [%4];"
        : "=r"(r[0]), "=r"(r[1]), "=r"(r[2]), "=r"(r[3]) : "r"(addr));
}
__device__ __forceinline__ void cpa16(unsigned dst, const void* src) {
    asm volatile("cp.async.cg.shared.global [%0], [%1], 16;" :: "r"(dst), "l"(src));
}
__device__ __forceinline__ void cpa_commit() { asm volatile("cp.async.commit_group;"); }
__device__ __forceinline__ void cpa_wait0()  { asm volatile("cp.async.wait_group 0;"); }
__device__ __forceinline__ float ex2f(float x) {
    float r; asm("ex2.approx.f32 %0, %1;" : "=f"(r) : "f"(x)); return r;
}
#define LOG2E 1.4426950408889634f
__device__ __forceinline__ float exp_nomax(float x) {
    return ex2f(fmaxf(x * LOG2E, -126.0f));
}

// ---------------------------------------------------------------------------
// Kernel 0: T5 bias LUT (exact integer bucket thresholds)
// ---------------------------------------------------------------------------
__global__ void bias_lut_kernel(const float* __restrict__ bias_table) {
    int idx = blockIdx.x * blockDim.x + threadIdx.x;
    if (idx >= H_ * 2 * S_) return;
    int h   = idx >> 12;
    int r   = idx & 4095;
    int rel = r - 2048;
    int bucket = (rel > 0) ? 16 : 0;
    int a = rel < 0 ? -rel : rel;
    int add;
    if      (a <  8) add = a;
    else if (a < 12) add = 8;
    else if (a < 16) add = 9;
    else if (a < 23) add = 10;
    else if (a < 32) add = 11;
    else if (a < 46) add = 12;
    else if (a < 64) add = 13;
    else if (a < 91) add = 14;
    else             add = 15;
    g_bias_lut[idx] = bias_table[(bucket + add) * H_ + h];
}

// ---------------------------------------------------------------------------
// Kernel 0a: Q,K -> packed row-major bf16 hi/lo planes
// ---------------------------------------------------------------------------
__global__ __launch_bounds__(256) void qk_prep_kernel(
    const float* __restrict__ Q, const float* __restrict__ K)
{
    int idx = blockIdx.x * 256 + threadIdx.x;
    const float2 q2 = *(const float2*)&Q[2 * (size_t)idx];
    const float2 k2 = *(const float2*)&K[2 * (size_t)idx];
    unsigned hi, lo;
    split_pack(q2.x, q2.y, hi, lo);
    g_Qh[idx] = hi; g_Ql[idx] = lo;
    split_pack(k2.x, k2.y, hi, lo);
    g_Kh[idx] = hi; g_Kl[idx] = lo;
}

// ---------------------------------------------------------------------------
// Kernel 0b: V -> packed transposed bf16 hi/lo planes [bh][chunk][d][kp]
// ---------------------------------------------------------------------------
__global__ __launch_bounds__(256) void v_prep_kernel(const float* __restrict__ V)
{
    __shared__ float Vs[64 * 68];
    int c  = blockIdx.x;
    int bh = blockIdx.y;
    int t  = threadIdx.x;
    const float* Vp = V + (size_t)bh * S_ * D_ + (size_t)c * 64 * D_;
    #pragma unroll
    for (int i = 0; i < 4; i++) {
        int idx = t + i * 256;
        int k = idx >> 4, d4 = idx & 15;
        *(float4*)&Vs[k * 68 + d4 * 4] = *(const float4*)&Vp[(size_t)k * D_ + d4 * 4];
    }
    __syncthreads();
    unsigned base = ((unsigned)bh * KBLK + c) * 64 * 32;
    #pragma unroll
    for (int i = 0; i < 8; i++) {
        int idx = t + i * 256;
        int d = idx >> 5, kp = idx & 31;
        unsigned hh, ll;
        split_pack(Vs[(2 * kp) * 68 + d], Vs[(2 * kp + 1) * 68 + d], hh, ll);
        g_Vth[base + d * 32 + kp] = hh;
        g_Vtl[base + d * 32 + kp] = ll;
    }
}

// ---------------------------------------------------------------------------
// Kernel 1: E = exp(QK^T/8 + bias + mask*-1e9) stored as bf16 hi/lo planes
// + partial row sums. Tile 128(q) x 128(k), 8 warps (4m x 2n).
// ---------------------------------------------------------------------------
#define QSTR 36
#define L_QH 0
#define L_QL (128 * QSTR)
#define L_KH (2 * 128 * QSTR)
#define L_KL (3 * 128 * QSTR)
#define L_LUT (4 * 128 * QSTR)
#define L_SMEM ((L_LUT + 288) * 4)

__global__ __launch_bounds__(256, 2) void logits_kernel(const int* __restrict__ mask)
{
    extern __shared__ unsigned smu[];
    float* sLut = (float*)(smu + L_LUT);

    int bh = blockIdx.z;
    int q0 = blockIdx.y * 128;
    int k0 = blockIdx.x * 128;
    int b  = bh >> 3;
    int h  = bh & 7;

    int t = threadIdx.x;
    int w = t >> 5, l = t & 31, g = l >> 2, tg = l & 3;
    int wm = w & 3, wn = w >> 2;

    int lbase = k0 - q0 + 2048 - 128;
    for (int i = t; i < 288; i += 256) {
        int ix = lbase + i;
        ix = ix < 0 ? 0 : (ix > 4095 ? 4095 : ix);
        sLut[i] = g_bias_lut[h * 4096 + ix];
    }

    unsigned sbase = (unsigned)__cvta_generic_to_shared(smu);
    unsigned qrow = (unsigned)bh * S_ + q0;
    unsigned krow = (unsigned)bh * S_ + k0;
    #pragma unroll
    for (int i = 0; i < 4; i++) {
        int idx = t + i * 256;
        int r = idx >> 3, sg = idx & 7;
        cpa16(sbase + (L_QH + r * QSTR + sg * 4) * 4, &g_Qh[(qrow + r) * 32 + sg * 4]);
        cpa16(sbase + (L_QL + r * QSTR + sg * 4) * 4, &g_Ql[(qrow + r) * 32 + sg * 4]);
        cpa16(sbase + (L_KH + r * QSTR + sg * 4) * 4, &g_Kh[(krow + r) * 32 + sg * 4]);
        cpa16(sbase + (L_KL + r * QSTR + sg * 4) * 4, &g_Kl[(krow + r) * 32 + sg * 4]);
    }
    cpa_commit(); cpa_wait0();
    __syncthreads();

    int lq = l & 7, lh8 = (l >> 3) & 1, lc = (l >> 4);
    int qd = l >> 3;
    unsigned aoff = ((wm * 32 + lh8 * 8 + lq) * QSTR + lc * 4) * 4;
    unsigned boff = ((wn * 64 + (qd >> 1) * 8 + lq) * QSTR + (qd & 1) * 4) * 4;

    float C[2][8][4] = {};

    #pragma unroll
    for (int ks = 0; ks < 4; ks++) {
        unsigned ah[2][4], al[2][4];
        #pragma unroll
        for (int mt = 0; mt < 2; mt++) {
            ldm4(ah[mt], sbase + L_QH * 4 + aoff + mt * (16 * QSTR * 4) + ks * 32);
            ldm4(al[mt], sbase + L_QL * 4 + aoff + mt * (16 * QSTR * 4) + ks * 32);
        }
        #pragma unroll
        for (int ntp = 0; ntp < 4; ntp++) {
            unsigned bhf[4], blf[4];
            ldm4(bhf, sbase + L_KH * 4 + boff + ntp * (16 * QSTR * 4) + ks * 32);
            ldm4(blf, sbase + L_KL * 4 + boff + ntp * (16 * QSTR * 4) + ks * 32);
            #pragma unroll
            for (int mt = 0; mt < 2; mt++) {
                mma16(C[mt][2 * ntp],     ah[mt], bhf);
                mma16(C[mt][2 * ntp],     ah[mt], blf);
                mma16(C[mt][2 * ntp],     al[mt], bhf);
                mma16(C[mt][2 * ntp + 1], ah[mt], bhf + 2);
                mma16(C[mt][2 * ntp + 1], ah[mt], blf + 2);
                mma16(C[mt][2 * ntp + 1], al[mt], bhf + 2);
            }
        }
    }

    // epilogue: exp, split to bf16 hi/lo planes, row sums
    float rsum[4] = {0.f, 0.f, 0.f, 0.f};
    #pragma unroll
    for (int nt = 0; nt < 8; nt++) {
        int kcol = k0 + wn * 64 + nt * 8 + 2 * tg;
        int jc = (kcol - k0) + 128;
        float mv0 = -1e9f * (float)mask[b * S_ + kcol];
        float mv1 = -1e9f * (float)mask[b * S_ + kcol + 1];
        #pragma unroll
        for (int mt = 0; mt < 2; mt++) {
            int q = q0 + wm * 32 + mt * 16 + g;
            int jq = jc - (q - q0);
            float e0 = exp_nomax(fmaf(C[mt][nt][0], 0.125f, sLut[jq]     + mv0));
            float e1 = exp_nomax(fmaf(C[mt][nt][1], 0.125f, sLut[jq + 1] + mv1));
            unsigned hh, ll;
            split_pack(e0, e1, hh, ll);
            size_t ei = ((size_t)bh * S_ + q) * 1024 + (kcol >> 1);
            g_Eh[ei] = hh; g_El[ei] = ll;
            int jq2 = jq - 8;
            float e2 = exp_nomax(fmaf(C[mt][nt][2], 0.125f, sLut[jq2]     + mv0));
            float e3 = exp_nomax(fmaf(C[mt][nt][3], 0.125f, sLut[jq2 + 1] + mv1));
            split_pack(e2, e3, hh, ll);
            size_t ei2 = ei + 8 * 1024;
            g_Eh[ei2] = hh; g_El[ei2] = ll;
            rsum[mt * 2]     += e0 + e1;
            rsum[mt * 2 + 1] += e2 + e3;
        }
    }
    #pragma unroll
    for (int ri = 0; ri < 4; ri++) {
        rsum[ri] += __shfl_xor_sync(0xffffffffu, rsum[ri], 1);
        rsum[ri] += __shfl_xor_sync(0xffffffffu, rsum[ri], 2);
    }
    __syncthreads();

    float* sSum = (float*)smu;   // [128][2]
    if (tg == 0) {
        #pragma unroll
        for (int ri = 0; ri < 4; ri++) {
            int rl = wm * 32 + (ri >> 1) * 16 + (ri & 1) * 8 + g;
            sSum[rl * 2 + wn] = rsum[ri];
        }
    }
    __syncthreads();
    if (t < 128)
        g_sums[((size_t)bh * S_ + q0 + t) * QBLK + blockIdx.x] = sSum[t * 2] + sSum[t * 2 + 1];
}

// ---------------------------------------------------------------------------
// Kernel 2: av. cp.async E and V planes (double-buffered); mma directly on
// them (O = E@V, scaled by invS at the end); reconstruct w=(hi+lo)*invS and
// store normalized weights once.
// ---------------------------------------------------------------------------
#define PSTR 36
#define A_PH 0
#define A_PL 4608
#define A_VH 9216
#define A_VL 13824
#define A_SI 18432
#define AV_SMEM ((A_SI + 64) * 4)   // 73984 B

__global__ __launch_bounds__(256, 2) void av_kernel(float* __restrict__ out)
{
    extern __shared__ unsigned smu[];
    float* sI = (float*)(smu + A_SI);

    int bh = blockIdx.y;
    int q0 = blockIdx.x * 64;

    float* Wp = out + OUT_OFF + (size_t)bh * S_ * S_;

    int t = threadIdx.x;
    int w = t >> 5, l = t & 31, g = l >> 2, tg = l & 3;
    int wm = w & 3, wn = w >> 2;

    unsigned sbase = (unsigned)__cvta_generic_to_shared(smu);

    int lq = l & 7, lh8 = (l >> 3) & 1, lc = (l >> 4);
    int qd = l >> 3;
    unsigned aoff = ((wm * 16 + lh8 * 8 + lq) * PSTR + lc * 4) * 4;
    unsigned boff = ((wn * 32 + (qd >> 1) * 8 + lq) * PSTR + (qd & 1) * 4) * 4;

    if (t < 64) {
        const float* ps = &g_sums[((size_t)bh * S_ + q0 + t) * QBLK];
        float s = 0.f;
        #pragma unroll
        for (int i = 0; i < QBLK; i++) s += ps[i];
        sI[t] = 1.0f / s;
    }

    // prefetch chunk 0 into stage 0
    {
        size_t erow = ((size_t)bh * S_ + q0);
        unsigned vb = (unsigned)bh * KBLK * 64 * 32;
        #pragma unroll
        for (int i = 0; i < 2; i++) {
            int idx = t + i * 256;
            int r = idx >> 3, sg = idx & 7;
            cpa16(sbase + (A_PH + r * PSTR + sg * 4) * 4, &g_Eh[(erow + r) * 1024 + sg * 4]);
            cpa16(sbase + (A_PL + r * PSTR + sg * 4) * 4, &g_El[(erow + r) * 1024 + sg * 4]);
            cpa16(sbase + (A_VH + r * PSTR + sg * 4) * 4, &g_Vth[vb + r * 32 + sg * 4]);
            cpa16(sbase + (A_VL + r * PSTR + sg * 4) * 4, &g_Vtl[vb + r * 32 + sg * 4]);
        }
        cpa_commit();
    }

    float C[4][4] = {};

    for (int kci = 0; kci < KBLK; kci++) {
        int kc = kci * 64;
        int st = kci & 1;
        cpa_wait0();
        __syncthreads();

        if (kci + 1 < KBLK) {
            int s = (kci + 1) & 1;
            size_t erow = ((size_t)bh * S_ + q0);
            int kc2n = (kc + 64) >> 1;
            unsigned vb = ((unsigned)bh * KBLK + kci + 1) * 64 * 32;
            #pragma unroll
            for (int i = 0; i < 2; i++) {
                int idx = t + i * 256;
                int r = idx >> 3, sg = idx & 7;
                cpa16(sbase + (A_PH + s * 2304 + r * PSTR + sg * 4) * 4,
                      &g_Eh[(erow + r) * 1024 + kc2n + sg * 4]);
                cpa16(sbase + (A_PL + s * 2304 + r * PSTR + sg * 4) * 4,
                      &g_El[(erow + r) * 1024 + kc2n + sg * 4]);
                cpa16(sbase + (A_VH + s * 2304 + r * PSTR + sg * 4) * 4,
                      &g_Vth[vb + r * 32 + sg * 4]);
                cpa16(sbase + (A_VL + s * 2304 + r * PSTR + sg * 4) * 4,
                      &g_Vtl[vb + r * 32 + sg * 4]);
            }
            cpa_commit();
        }

        // --- mma straight off the async-filled planes ---
        unsigned phb = (A_PH + st * 2304) * 4;
        unsigned plb = (A_PL + st * 2304) * 4;
        unsigned vhb = (A_VH + st * 2304) * 4;
        unsigned vlb = (A_VL + st * 2304) * 4;
        #pragma unroll
        for (int ks = 0; ks < 4; ks++) {
            unsigned ah[4], al[4];
            ldm4(ah, sbase + phb + aoff + ks * 32);
            ldm4(al, sbase + plb + aoff + ks * 32);
            #pragma unroll
            for (int ntp = 0; ntp < 2; ntp++) {
                unsigned bhf[4], blf[4];
                ldm4(bhf, sbase + vhb + boff + ntp * (16 * PSTR * 4) + ks * 32);
                ldm4(blf, sbase + vlb + boff + ntp * (16 * PSTR * 4) + ks * 32);
                mma16(C[2 * ntp],     ah, bhf);
                mma16(C[2 * ntp],     ah, blf);
                mma16(C[2 * ntp],     al, bhf);
                mma16(C[2 * ntp + 1], ah, bhf + 2);
                mma16(C[2 * ntp + 1], ah, blf + 2);
                mma16(C[2 * ntp + 1], al, bhf + 2);
            }
        }

        // --- reconstruct and store normalized weights (fire-and-forget) ---
        #pragma unroll
        for (int i = 0; i < 2; i++) {
            int idx = t + i * 256;
            int r = idx >> 3, c4 = idx & 7;
            uint4 hu = *(uint4*)&smu[A_PH + st * 2304 + r * PSTR + c4 * 4];
            uint4 lu = *(uint4*)&smu[A_PL + st * 2304 + r * PSTR + c4 * 4];
            float I = sI[r];
            float4 w0, w1;
            float2 fh, fl;
            fh = __bfloat1622float2(*(__nv_bfloat162*)&hu.x);
            fl = __bfloat1622float2(*(__nv_bfloat162*)&lu.x);
            w0.x = (fh.x + fl.x) * I; w0.y = (fh.y + fl.y) * I;
            fh = __bfloat1622float2(*(__nv_bfloat162*)&hu.y);
            fl = __bfloat1622float2(*(__nv_bfloat162*)&lu.y);
            w0.z = (fh.x + fl.x) * I; w0.w = (fh.y + fl.y) * I;
            fh = __bfloat1622float2(*(__nv_bfloat162*)&hu.z);
            fl = __bfloat1622float2(*(__nv_bfloat162*)&lu.z);
            w1.x = (fh.x + fl.x) * I; w1.y = (fh.y + fl.y) * I;
            fh = __bfloat1622float2(*(__nv_bfloat162*)&hu.w);
            fl = __bfloat1622float2(*(__nv_bfloat162*)&lu.w);
            w1.z = (fh.x + fl.x) * I; w1.w = (fh.y + fl.y) * I;
            float* wp = &Wp[(size_t)(q0 + r) * S_ + kc + c4 * 8];
            *(float4*)wp       = w0;
            *(float4*)(wp + 4) = w1;
        }
        __syncthreads();
    }

    // scale O by invS, store
    float Ilo = sI[wm * 16 + g];
    float Ihi = sI[wm * 16 + g + 8];
    #pragma unroll
    for (int nt = 0; nt < 4; nt++) {
        int d = wn * 32 + nt * 8 + 2 * tg;
        int q = q0 + wm * 16 + g;
        *(float2*)&out[((size_t)bh * S_ + q) * D_ + d] =
            make_float2(C[nt][0] * Ilo, C[nt][1] * Ilo);
        *(float2*)&out[((size_t)bh * S_ + q + 8) * D_ + d] =
            make_float2(C[nt][2] * Ihi, C[nt][3] * Ihi);
    }
}

// ---------------------------------------------------------------------------
extern "C" void kernel_launch(void* const* d_in, const int* in_sizes, int n_in,
                              void* d_out, int out_size)
{
    const float* Q    = (const float*)d_in[0];
    const float* K    = (const float*)d_in[1];
    const float* V    = (const float*)d_in[2];
    const int*   mask = (const int*)d_in[3];
    const float* bt   = (const float*)d_in[4];
    float* out = (float*)d_out;

    cudaFuncSetAttribute(logits_kernel, cudaFuncAttributeMaxDynamicSharedMemorySize, L_SMEM);
    cudaFuncSetAttribute(av_kernel,     cudaFuncAttributeMaxDynamicSharedMemorySize, AV_SMEM);

    bias_lut_kernel<<<32, 1024>>>(bt);
    qk_prep_kernel<<<BH_ * S_ * 32 / 256, 256>>>(Q, K);
    dim3 gv(KBLK, BH_);
    v_prep_kernel<<<gv, 256>>>(V);

    dim3 g1(S_ / 128, S_ / 128, BH_);   // (16, 16, 16)
    logits_kernel<<<g1, 256, L_SMEM>>>(mask);

    dim3 g2(S_ / 64, BH_);              // (32, 16)
    av_kernel<<<g2, 256, AV_SMEM>>>(out);
}

// round 13
// speedup vs baseline: 1.1282x; 1.1165x over previous
#include <cuda_runtime.h>
#include <cuda_bf16.h>
#include <cstdint>

#define B_ 2
#define H_ 8
#define S_ 2048
#define D_ 64
#define BH_ (B_ * H_)
#define OUT_OFF ((size_t)B_ * H_ * S_ * D_)   // output tensor first, then weights
#define KBLK 32                                // av chunks (64 wide)
#define QBLK 16                                // logits k-blocks (128 wide)

__device__ float  g_bias_lut[H_ * 2 * S_];
__device__ float  g_sums[BH_ * S_ * QBLK];    // per (row, 128-kblock) partial expsum
// packed bf16 hi/lo planes
__device__ unsigned g_Qh[BH_ * S_ * 32];
__device__ unsigned g_Ql[BH_ * S_ * 32];
__device__ unsigned g_Kh[BH_ * S_ * 32];
__device__ unsigned g_Kl[BH_ * S_ * 32];
__device__ unsigned g_Vth[BH_ * KBLK * 64 * 32];   // [bh][chunk][d][kpair]
__device__ unsigned g_Vtl[BH_ * KBLK * 64 * 32];

// ---- helpers ----------------------------------------------------------------
__device__ __forceinline__ void split_pack(float x0, float x1, unsigned& hi, unsigned& lo) {
    __nv_bfloat162 h = __floats2bfloat162_rn(x0, x1);
    float f0 = __bfloat162float(__low2bfloat16(h));
    float f1 = __bfloat162float(__high2bfloat16(h));
    __nv_bfloat162 l = __floats2bfloat162_rn(x0 - f0, x1 - f1);
    hi = *reinterpret_cast<unsigned*>(&h);
    lo = *reinterpret_cast<unsigned*>(&l);
}
__device__ __forceinline__ void mma16(float* d, const unsigned* a, const unsigned* b) {
    asm("mma.sync.aligned.m16n8k16.row.col.f32.bf16.bf16.f32 "
        "{%0,%1,%2,%3},{%4,%5,%6,%7},{%8,%9},{%0,%1,%2,%3};"
        : "+f"(d[0]), "+f"(d[1]), "+f"(d[2]), "+f"(d[3])
        : "r"(a[0]), "r"(a[1]), "r"(a[2]), "r"(a[3]), "r"(b[0]), "r"(b[1]));
}
__device__ __forceinline__ void ldm4(unsigned* r, unsigned addr) {
    asm volatile("ldmatrix.sync.aligned.m8n8.x4.shared.b16 {%0,%1,%2,%3}, [%4];"
        : "=r"(r[0]), "=r"(r[1]), "=r"(r[2]), "=r"(r[3]) : "r"(addr));
}
__device__ __forceinline__ void cpa16(unsigned dst, const void* src) {
    asm volatile("cp.async.cg.shared.global [%0], [%1], 16;" :: "r"(dst), "l"(src));
}
__device__ __forceinline__ void cpa_commit() { asm volatile("cp.async.commit_group;"); }
__device__ __forceinline__ void cpa_wait0()  { asm volatile("cp.async.wait_group 0;"); }
__device__ __forceinline__ float ex2f(float x) {
    float r; asm("ex2.approx.f32 %0, %1;" : "=f"(r) : "f"(x)); return r;
}
#define LOG2E 1.4426950408889634f
__device__ __forceinline__ float exp_nomax(float x) {
    return ex2f(fmaxf(x * LOG2E, -126.0f));
}

// ---------------------------------------------------------------------------
// Kernel 0: T5 bias LUT (exact integer bucket thresholds)
// ---------------------------------------------------------------------------
__global__ void bias_lut_kernel(const float* __restrict__ bias_table) {
    int idx = blockIdx.x * blockDim.x + threadIdx.x;
    if (idx >= H_ * 2 * S_) return;
    int h   = idx >> 12;
    int r   = idx & 4095;
    int rel = r - 2048;
    int bucket = (rel > 0) ? 16 : 0;
    int a = rel < 0 ? -rel : rel;
    int add;
    if      (a <  8) add = a;
    else if (a < 12) add = 8;
    else if (a < 16) add = 9;
    else if (a < 23) add = 10;
    else if (a < 32) add = 11;
    else if (a < 46) add = 12;
    else if (a < 64) add = 13;
    else if (a < 91) add = 14;
    else             add = 15;
    g_bias_lut[idx] = bias_table[(bucket + add) * H_ + h];
}

// ---------------------------------------------------------------------------
// Kernel 0a: Q,K -> packed row-major bf16 hi/lo planes
// ---------------------------------------------------------------------------
__global__ __launch_bounds__(256) void qk_prep_kernel(
    const float* __restrict__ Q, const float* __restrict__ K)
{
    int idx = blockIdx.x * 256 + threadIdx.x;
    const float2 q2 = *(const float2*)&Q[2 * (size_t)idx];
    const float2 k2 = *(const float2*)&K[2 * (size_t)idx];
    unsigned hi, lo;
    split_pack(q2.x, q2.y, hi, lo);
    g_Qh[idx] = hi; g_Ql[idx] = lo;
    split_pack(k2.x, k2.y, hi, lo);
    g_Kh[idx] = hi; g_Kl[idx] = lo;
}

// ---------------------------------------------------------------------------
// Kernel 0b: V -> packed transposed bf16 hi/lo planes [bh][chunk][d][kp]
// ---------------------------------------------------------------------------
__global__ __launch_bounds__(256) void v_prep_kernel(const float* __restrict__ V)
{
    __shared__ float Vs[64 * 68];
    int c  = blockIdx.x;
    int bh = blockIdx.y;
    int t  = threadIdx.x;
    const float* Vp = V + (size_t)bh * S_ * D_ + (size_t)c * 64 * D_;
    #pragma unroll
    for (int i = 0; i < 4; i++) {
        int idx = t + i * 256;
        int k = idx >> 4, d4 = idx & 15;
        *(float4*)&Vs[k * 68 + d4 * 4] = *(const float4*)&Vp[(size_t)k * D_ + d4 * 4];
    }
    __syncthreads();
    unsigned base = ((unsigned)bh * KBLK + c) * 64 * 32;
    #pragma unroll
    for (int i = 0; i < 8; i++) {
        int idx = t + i * 256;
        int d = idx >> 5, kp = idx & 31;
        unsigned hh, ll;
        split_pack(Vs[(2 * kp) * 68 + d], Vs[(2 * kp + 1) * 68 + d], hh, ll);
        g_Vth[base + d * 32 + kp] = hh;
        g_Vtl[base + d * 32 + kp] = ll;
    }
}

// ---------------------------------------------------------------------------
// Kernel 1: writes expW = exp(QK^T/8 + bias + mask*-1e9) + partial row sums.
// Tile 128(q) x 128(k), 8 warps (4m x 2n). Epilogue stages the fp32 tile in
// smem (stride 136, conflict-free) and emits coalesced 128B row stores.
// ---------------------------------------------------------------------------
#define QSTR 36
#define L_QH 0
#define L_QL (128 * QSTR)
#define L_KH (2 * 128 * QSTR)
#define L_KL (3 * 128 * QSTR)
#define L_LUT (4 * 128 * QSTR)
#define L_SMEM ((L_LUT + 288) * 4)
#define WSTR 136                         // staging stride (floats)

__global__ __launch_bounds__(256, 2) void logits_kernel(
    const int* __restrict__ mask, float* __restrict__ out)
{
    extern __shared__ unsigned smu[];
    float* sLut = (float*)(smu + L_LUT);

    int bh = blockIdx.z;
    int q0 = blockIdx.y * 128;
    int k0 = blockIdx.x * 128;
    int b  = bh >> 3;
    int h  = bh & 7;

    int t = threadIdx.x;
    int w = t >> 5, l = t & 31, g = l >> 2, tg = l & 3;
    int wm = w & 3, wn = w >> 2;

    int lbase = k0 - q0 + 2048 - 128;
    for (int i = t; i < 288; i += 256) {
        int ix = lbase + i;
        ix = ix < 0 ? 0 : (ix > 4095 ? 4095 : ix);
        sLut[i] = g_bias_lut[h * 4096 + ix];
    }

    unsigned sbase = (unsigned)__cvta_generic_to_shared(smu);
    unsigned qrow = (unsigned)bh * S_ + q0;
    unsigned krow = (unsigned)bh * S_ + k0;
    #pragma unroll
    for (int i = 0; i < 4; i++) {
        int idx = t + i * 256;
        int r = idx >> 3, sg = idx & 7;
        cpa16(sbase + (L_QH + r * QSTR + sg * 4) * 4, &g_Qh[(qrow + r) * 32 + sg * 4]);
        cpa16(sbase + (L_QL + r * QSTR + sg * 4) * 4, &g_Ql[(qrow + r) * 32 + sg * 4]);
        cpa16(sbase + (L_KH + r * QSTR + sg * 4) * 4, &g_Kh[(krow + r) * 32 + sg * 4]);
        cpa16(sbase + (L_KL + r * QSTR + sg * 4) * 4, &g_Kl[(krow + r) * 32 + sg * 4]);
    }
    cpa_commit(); cpa_wait0();
    __syncthreads();

    int lq = l & 7, lh8 = (l >> 3) & 1, lc = (l >> 4);
    int qd = l >> 3;
    unsigned aoff = ((wm * 32 + lh8 * 8 + lq) * QSTR + lc * 4) * 4;
    unsigned boff = ((wn * 64 + (qd >> 1) * 8 + lq) * QSTR + (qd & 1) * 4) * 4;

    float C[2][8][4] = {};

    #pragma unroll
    for (int ks = 0; ks < 4; ks++) {
        unsigned ah[2][4], al[2][4];
        #pragma unroll
        for (int mt = 0; mt < 2; mt++) {
            ldm4(ah[mt], sbase + L_QH * 4 + aoff + mt * (16 * QSTR * 4) + ks * 32);
            ldm4(al[mt], sbase + L_QL * 4 + aoff + mt * (16 * QSTR * 4) + ks * 32);
        }
        #pragma unroll
        for (int ntp = 0; ntp < 4; ntp++) {
            unsigned bhf[4], blf[4];
            ldm4(bhf, sbase + L_KH * 4 + boff + ntp * (16 * QSTR * 4) + ks * 32);
            ldm4(blf, sbase + L_KL * 4 + boff + ntp * (16 * QSTR * 4) + ks * 32);
            #pragma unroll
            for (int mt = 0; mt < 2; mt++) {
                mma16(C[mt][2 * ntp],     ah[mt], bhf);
                mma16(C[mt][2 * ntp],     ah[mt], blf);
                mma16(C[mt][2 * ntp],     al[mt], bhf);
                mma16(C[mt][2 * ntp + 1], ah[mt], bhf + 2);
                mma16(C[mt][2 * ntp + 1], ah[mt], blf + 2);
                mma16(C[mt][2 * ntp + 1], al[mt], bhf + 2);
            }
        }
    }

    __syncthreads();   // all warps done reading Q/K planes before staging reuse

    // epilogue: exp + stage into smem (stride 136) + row sums
    float* sW = (float*)smu;            // 128 * 136 floats = 69632 B
    float rsum[4] = {0.f, 0.f, 0.f, 0.f};
    #pragma unroll
    for (int nt = 0; nt < 8; nt++) {
        int kk = wn * 64 + nt * 8 + 2 * tg;     // col within tile
        int kcol = k0 + kk;
        int jc = kk + 128;
        float mv0 = -1e9f * (float)mask[b * S_ + kcol];
        float mv1 = -1e9f * (float)mask[b * S_ + kcol + 1];
        #pragma unroll
        for (int mt = 0; mt < 2; mt++) {
            int qq = wm * 32 + mt * 16 + g;     // row within tile
            int jq = jc - qq;
            float e0 = exp_nomax(fmaf(C[mt][nt][0], 0.125f, sLut[jq]     + mv0));
            float e1 = exp_nomax(fmaf(C[mt][nt][1], 0.125f, sLut[jq + 1] + mv1));
            *(float2*)&sW[qq * WSTR + kk] = make_float2(e0, e1);
            int jq2 = jq - 8;
            float e2 = exp_nomax(fmaf(C[mt][nt][2], 0.125f, sLut[jq2]     + mv0));
            float e3 = exp_nomax(fmaf(C[mt][nt][3], 0.125f, sLut[jq2 + 1] + mv1));
            *(float2*)&sW[(qq + 8) * WSTR + kk] = make_float2(e2, e3);
            rsum[mt * 2]     += e0 + e1;
            rsum[mt * 2 + 1] += e2 + e3;
        }
    }
    __syncthreads();

    // coalesced stores: each row = 512B contiguous
    float* wbase = out + OUT_OFF + (size_t)bh * S_ * S_ + k0;
    #pragma unroll
    for (int i = 0; i < 16; i++) {
        int idx = t + i * 256;
        int row = idx >> 5, seg = idx & 31;
        float4 v = *(float4*)&sW[row * WSTR + seg * 4];
        *(float4*)&wbase[(size_t)(q0 + row) * S_ + seg * 4] = v;
    }

    #pragma unroll
    for (int ri = 0; ri < 4; ri++) {
        rsum[ri] += __shfl_xor_sync(0xffffffffu, rsum[ri], 1);
        rsum[ri] += __shfl_xor_sync(0xffffffffu, rsum[ri], 2);
    }
    __syncthreads();

    float* sSum = (float*)smu + 128 * WSTR;   // after staged tile (fits: 17408+256 < 18432)
    if (tg == 0) {
        #pragma unroll
        for (int ri = 0; ri < 4; ri++) {
            int rl = wm * 32 + (ri >> 1) * 16 + (ri & 1) * 8 + g;
            sSum[rl * 2 + wn] = rsum[ri];
        }
    }
    __syncthreads();
    if (t < 128)
        g_sums[((size_t)bh * S_ + q0 + t) * QBLK + blockIdx.x] = sSum[t * 2] + sSum[t * 2 + 1];
}

// ---------------------------------------------------------------------------
// Kernel 2: av (identical to R10 best). Reads expW (cp.async double-buffered),
// scales by invS, writes normalized weights once, P@V via ldmatrix + mma.
// ---------------------------------------------------------------------------
#define PSTR 36
#define RAWSTR 68
#define OFF_RAW   0
#define OFF_PH    (2 * 64 * RAWSTR)
#define OFF_PL    (OFF_PH + 64 * PSTR)
#define OFF_VH    (OFF_PL + 64 * PSTR)
#define OFF_VL    (OFF_VH + 2 * 64 * PSTR)
#define OFF_ST    (OFF_VL + 2 * 64 * PSTR)
#define AV_SMEM   ((OFF_ST + 64) * 4)

__global__ __launch_bounds__(256) void av_kernel(
    float* __restrict__ W, float* __restrict__ out)
{
    extern __shared__ unsigned smu[];
    float*    rawW = (float*)smu;
    unsigned* Ph   = smu + OFF_PH;
    unsigned* Pl   = smu + OFF_PL;
    float*    sI   = (float*)(smu + OFF_ST);

    int bh = blockIdx.y;
    int q0 = blockIdx.x * 64;

    float* Wp = W + OUT_OFF + (size_t)bh * S_ * S_;

    int t = threadIdx.x;
    int w = t >> 5, l = t & 31, g = l >> 2, tg = l & 3;
    int wm = w & 3, wn = w >> 2;

    unsigned sbase = (unsigned)__cvta_generic_to_shared(smu);

    int lq = l & 7, lh8 = (l >> 3) & 1, lc = (l >> 4);
    int qd = l >> 3;
    unsigned aoff = ((wm * 16 + lh8 * 8 + lq) * PSTR + lc * 4) * 4;
    unsigned boff = ((wn * 32 + (qd >> 1) * 8 + lq) * PSTR + (qd & 1) * 4) * 4;

    if (t < 64) {
        const float* ps = &g_sums[((size_t)bh * S_ + q0 + t) * QBLK];
        float s = 0.f;
        #pragma unroll
        for (int i = 0; i < QBLK; i++) s += ps[i];
        sI[t] = 1.0f / s;
    }

    // prefetch chunk 0 into stage 0
    {
        #pragma unroll
        for (int i = 0; i < 4; i++) {
            int idx = t + i * 256;
            int r = idx >> 4, c4 = idx & 15;
            cpa16(sbase + (OFF_RAW + r * RAWSTR + c4 * 4) * 4,
                  &Wp[(size_t)(q0 + r) * S_ + c4 * 4]);
        }
        unsigned vb = (unsigned)bh * KBLK * 64 * 32;
        #pragma unroll
        for (int i = 0; i < 2; i++) {
            int idx = t + i * 256;
            int d = idx >> 3, sg = idx & 7;
            cpa16(sbase + (OFF_VH + d * PSTR + sg * 4) * 4, &g_Vth[vb + d * 32 + sg * 4]);
            cpa16(sbase + (OFF_VL + d * PSTR + sg * 4) * 4, &g_Vtl[vb + d * 32 + sg * 4]);
        }
        cpa_commit();
    }

    float C[4][4] = {};

    for (int kci = 0; kci < KBLK; kci++) {
        int kc = kci * 64;
        int st = kci & 1;
        cpa_wait0();
        __syncthreads();

        if (kci + 1 < KBLK) {
            int s = (kci + 1) & 1;
            #pragma unroll
            for (int i = 0; i < 4; i++) {
                int idx = t + i * 256;
                int r = idx >> 4, c4 = idx & 15;
                cpa16(sbase + (OFF_RAW + s * 64 * RAWSTR + r * RAWSTR + c4 * 4) * 4,
                      &Wp[(size_t)(q0 + r) * S_ + kc + 64 + c4 * 4]);
            }
            unsigned vb = ((unsigned)bh * KBLK + kci + 1) * 64 * 32;
            #pragma unroll
            for (int i = 0; i < 2; i++) {
                int idx = t + i * 256;
                int d = idx >> 3, sg = idx & 7;
                cpa16(sbase + (OFF_VH + s * 64 * PSTR + d * PSTR + sg * 4) * 4,
                      &g_Vth[vb + d * 32 + sg * 4]);
                cpa16(sbase + (OFF_VL + s * 64 * PSTR + d * PSTR + sg * 4) * 4,
                      &g_Vtl[vb + d * 32 + sg * 4]);
            }
            cpa_commit();
        }

        // fill P: p = expW * invS; write normalized; pack
        #pragma unroll
        for (int i = 0; i < 4; i++) {
            int idx = t + i * 256;
            int q = idx >> 4, f4 = idx & 15;
            float4 wv = *(const float4*)&rawW[st * 64 * RAWSTR + q * RAWSTR + f4 * 4];
            float I = sI[q];
            float p0 = wv.x * I, p1 = wv.y * I, p2 = wv.z * I, p3 = wv.w * I;
            *(float4*)&Wp[(size_t)(q0 + q) * S_ + kc + f4 * 4] = make_float4(p0, p1, p2, p3);
            unsigned h0, l0, h1, l1;
            split_pack(p0, p1, h0, l0);
            split_pack(p2, p3, h1, l1);
            *(uint2*)&Ph[q * PSTR + 2 * f4] = make_uint2(h0, h1);
            *(uint2*)&Pl[q * PSTR + 2 * f4] = make_uint2(l0, l1);
        }
        __syncthreads();

        unsigned vhb = (OFF_VH + st * 64 * PSTR) * 4;
        unsigned vlb = (OFF_VL + st * 64 * PSTR) * 4;
        #pragma unroll
        for (int ks = 0; ks < 4; ks++) {
            unsigned ah[4], al[4];
            ldm4(ah, sbase + OFF_PH * 4 + aoff + ks * 32);
            ldm4(al, sbase + OFF_PL * 4 + aoff + ks * 32);
            #pragma unroll
            for (int ntp = 0; ntp < 2; ntp++) {
                unsigned bhf[4], blf[4];
                ldm4(bhf, sbase + vhb + boff + ntp * (16 * PSTR * 4) + ks * 32);
                ldm4(blf, sbase + vlb + boff + ntp * (16 * PSTR * 4) + ks * 32);
                mma16(C[2 * ntp],     ah, bhf);
                mma16(C[2 * ntp],     ah, blf);
                mma16(C[2 * ntp],     al, bhf);
                mma16(C[2 * ntp + 1], ah, bhf + 2);
                mma16(C[2 * ntp + 1], ah, blf + 2);
                mma16(C[2 * ntp + 1], al, bhf + 2);
            }
        }
        __syncthreads();
    }

    #pragma unroll
    for (int nt = 0; nt < 4; nt++) {
        int d = wn * 32 + nt * 8 + 2 * tg;
        int q = q0 + wm * 16 + g;
        *(float2*)&out[((size_t)bh * S_ + q) * D_ + d]     = make_float2(C[nt][0], C[nt][1]);
        *(float2*)&out[((size_t)bh * S_ + q + 8) * D_ + d] = make_float2(C[nt][2], C[nt][3]);
    }
}

// ---------------------------------------------------------------------------
extern "C" void kernel_launch(void* const* d_in, const int* in_sizes, int n_in,
                              void* d_out, int out_size)
{
    const float* Q    = (const float*)d_in[0];
    const float* K    = (const float*)d_in[1];
    const float* V    = (const float*)d_in[2];
    const int*   mask = (const int*)d_in[3];
    const float* bt   = (const float*)d_in[4];
    float* out = (float*)d_out;

    cudaFuncSetAttribute(logits_kernel, cudaFuncAttributeMaxDynamicSharedMemorySize, L_SMEM);
    cudaFuncSetAttribute(av_kernel,     cudaFuncAttributeMaxDynamicSharedMemorySize, AV_SMEM);

    bias_lut_kernel<<<32, 1024>>>(bt);
    qk_prep_kernel<<<BH_ * S_ * 32 / 256, 256>>>(Q, K);
    dim3 gv(KBLK, BH_);
    v_prep_kernel<<<gv, 256>>>(V);

    dim3 g1(S_ / 128, S_ / 128, BH_);   // (16, 16, 16)
    logits_kernel<<<g1, 256, L_SMEM>>>(mask, out);

    dim3 g2(S_ / 64, BH_);              // (32, 16)
    av_kernel<<<g2, 256, AV_SMEM>>>(out, out);
}

// round 14
// speedup vs baseline: 1.2772x; 1.1321x over previous
#include <cuda_runtime.h>
#include <cuda_bf16.h>
#include <cstdint>

#define B_ 2
#define H_ 8
#define S_ 2048
#define D_ 64
#define BH_ (B_ * H_)
#define OUT_OFF ((size_t)B_ * H_ * S_ * D_)   // output tensor first, then weights
#define KBLK 32                                // av chunks (64 wide)
#define QBLK 16                                // logits k-blocks (128 wide)

__device__ float  g_bias_lut[H_ * 2 * S_];
__device__ float  g_sums[BH_ * S_ * QBLK];    // per (row, 128-kblock) partial expsum
// packed bf16 hi/lo planes
__device__ unsigned g_Qh[BH_ * S_ * 32];
__device__ unsigned g_Ql[BH_ * S_ * 32];
__device__ unsigned g_Kh[BH_ * S_ * 32];
__device__ unsigned g_Kl[BH_ * S_ * 32];
__device__ unsigned g_Vth[BH_ * KBLK * 64 * 32];   // [bh][chunk][d][kpair]
__device__ unsigned g_Vtl[BH_ * KBLK * 64 * 32];

// ---- helpers ----------------------------------------------------------------
__device__ __forceinline__ void split_pack(float x0, float x1, unsigned& hi, unsigned& lo) {
    __nv_bfloat162 h = __floats2bfloat162_rn(x0, x1);
    float f0 = __bfloat162float(__low2bfloat16(h));
    float f1 = __bfloat162float(__high2bfloat16(h));
    __nv_bfloat162 l = __floats2bfloat162_rn(x0 - f0, x1 - f1);
    hi = *reinterpret_cast<unsigned*>(&h);
    lo = *reinterpret_cast<unsigned*>(&l);
}
__device__ __forceinline__ void mma16(float* d, const unsigned* a, const unsigned* b) {
    asm("mma.sync.aligned.m16n8k16.row.col.f32.bf16.bf16.f32 "
        "{%0,%1,%2,%3},{%4,%5,%6,%7},{%8,%9},{%0,%1,%2,%3};"
        : "+f"(d[0]), "+f"(d[1]), "+f"(d[2]), "+f"(d[3])
        : "r"(a[0]), "r"(a[1]), "r"(a[2]), "r"(a[3]), "r"(b[0]), "r"(b[1]));
}
__device__ __forceinline__ void ldm4(unsigned* r, unsigned addr) {
    asm volatile("ldmatrix.sync.aligned.m8n8.x4.shared.b16 {%0,%1,%2,%3}, [%4];"
        : "=r"(r[0]), "=r"(r[1]), "=r"(r[2]), "=r"(r[3]) : "r"(addr));
}
__device__ __forceinline__ void cpa16(unsigned dst, const void* src) {
    asm volatile("cp.async.cg.shared.global [%0], [%1], 16;" :: "r"(dst), "l"(src));
}
__device__ __forceinline__ void cpa_commit() { asm volatile("cp.async.commit_group;"); }
__device__ __forceinline__ void cpa_wait0()  { asm volatile("cp.async.wait_group 0;"); }
__device__ __forceinline__ float ex2f(float x) {
    float r; asm("ex2.approx.f32 %0, %1;" : "=f"(r) : "f"(x)); return r;
}
__device__ __forceinline__ void stg2_cs(float* p, float x, float y) {
    asm volatile("st.global.cs.v2.f32 [%0], {%1, %2};" :: "l"(p), "f"(x), "f"(y) : "memory");
}
__device__ __forceinline__ void stg4_cs(float* p, float4 v) {
    asm volatile("st.global.cs.v4.f32 [%0], {%1, %2, %3, %4};"
                 :: "l"(p), "f"(v.x), "f"(v.y), "f"(v.z), "f"(v.w) : "memory");
}
#define LOG2E 1.4426950408889634f
__device__ __forceinline__ float exp_nomax(float x) {
    return ex2f(fmaxf(x * LOG2E, -126.0f));
}

// ---------------------------------------------------------------------------
// Kernel 0: T5 bias LUT (exact integer bucket thresholds)
// ---------------------------------------------------------------------------
__global__ void bias_lut_kernel(const float* __restrict__ bias_table) {
    int idx = blockIdx.x * blockDim.x + threadIdx.x;
    if (idx >= H_ * 2 * S_) return;
    int h   = idx >> 12;
    int r   = idx & 4095;
    int rel = r - 2048;
    int bucket = (rel > 0) ? 16 : 0;
    int a = rel < 0 ? -rel : rel;
    int add;
    if      (a <  8) add = a;
    else if (a < 12) add = 8;
    else if (a < 16) add = 9;
    else if (a < 23) add = 10;
    else if (a < 32) add = 11;
    else if (a < 46) add = 12;
    else if (a < 64) add = 13;
    else if (a < 91) add = 14;
    else             add = 15;
    g_bias_lut[idx] = bias_table[(bucket + add) * H_ + h];
}

// ---------------------------------------------------------------------------
// Kernel 0a: Q,K -> packed row-major bf16 hi/lo planes
// ---------------------------------------------------------------------------
__global__ __launch_bounds__(256) void qk_prep_kernel(
    const float* __restrict__ Q, const float* __restrict__ K)
{
    int idx = blockIdx.x * 256 + threadIdx.x;
    const float2 q2 = *(const float2*)&Q[2 * (size_t)idx];
    const float2 k2 = *(const float2*)&K[2 * (size_t)idx];
    unsigned hi, lo;
    split_pack(q2.x, q2.y, hi, lo);
    g_Qh[idx] = hi; g_Ql[idx] = lo;
    split_pack(k2.x, k2.y, hi, lo);
    g_Kh[idx] = hi; g_Kl[idx] = lo;
}

// ---------------------------------------------------------------------------
// Kernel 0b: V -> packed transposed bf16 hi/lo planes [bh][chunk][d][kp]
// ---------------------------------------------------------------------------
__global__ __launch_bounds__(256) void v_prep_kernel(const float* __restrict__ V)
{
    __shared__ float Vs[64 * 68];
    int c  = blockIdx.x;
    int bh = blockIdx.y;
    int t  = threadIdx.x;
    const float* Vp = V + (size_t)bh * S_ * D_ + (size_t)c * 64 * D_;
    #pragma unroll
    for (int i = 0; i < 4; i++) {
        int idx = t + i * 256;
        int k = idx >> 4, d4 = idx & 15;
        *(float4*)&Vs[k * 68 + d4 * 4] = *(const float4*)&Vp[(size_t)k * D_ + d4 * 4];
    }
    __syncthreads();
    unsigned base = ((unsigned)bh * KBLK + c) * 64 * 32;
    #pragma unroll
    for (int i = 0; i < 8; i++) {
        int idx = t + i * 256;
        int d = idx >> 5, kp = idx & 31;
        unsigned hh, ll;
        split_pack(Vs[(2 * kp) * 68 + d], Vs[(2 * kp + 1) * 68 + d], hh, ll);
        g_Vth[base + d * 32 + kp] = hh;
        g_Vtl[base + d * 32 + kp] = ll;
    }
}

// ---------------------------------------------------------------------------
// Kernel 1: writes expW = exp(QK^T/8 + bias + mask*-1e9) + partial row sums.
// Tile 128(q) x 128(k), 8 warps (4m x 2n). R10 epilogue (direct scatter) with
// smem mask window and .cs streaming stores.
// ---------------------------------------------------------------------------
#define QSTR 36
#define L_QH 0
#define L_QL (128 * QSTR)
#define L_KH (2 * 128 * QSTR)
#define L_KL (3 * 128 * QSTR)
#define L_LUT (4 * 128 * QSTR)
#define L_MSK (L_LUT + 288)
#define L_SMEM ((L_MSK + 128) * 4)

__global__ __launch_bounds__(256, 2) void logits_kernel(
    const int* __restrict__ mask, float* __restrict__ out)
{
    extern __shared__ unsigned smu[];
    float* sLut = (float*)(smu + L_LUT);
    float* sMsk = (float*)(smu + L_MSK);

    int bh = blockIdx.z;
    int q0 = blockIdx.y * 128;
    int k0 = blockIdx.x * 128;
    int b  = bh >> 3;
    int h  = bh & 7;

    int t = threadIdx.x;
    int w = t >> 5, l = t & 31, g = l >> 2, tg = l & 3;
    int wm = w & 3, wn = w >> 2;

    int lbase = k0 - q0 + 2048 - 128;
    for (int i = t; i < 288; i += 256) {
        int ix = lbase + i;
        ix = ix < 0 ? 0 : (ix > 4095 ? 4095 : ix);
        sLut[i] = g_bias_lut[h * 4096 + ix];
    }
    if (t < 128)
        sMsk[t] = -1e9f * (float)mask[b * S_ + k0 + t];

    unsigned sbase = (unsigned)__cvta_generic_to_shared(smu);
    unsigned qrow = (unsigned)bh * S_ + q0;
    unsigned krow = (unsigned)bh * S_ + k0;
    #pragma unroll
    for (int i = 0; i < 4; i++) {
        int idx = t + i * 256;
        int r = idx >> 3, sg = idx & 7;
        cpa16(sbase + (L_QH + r * QSTR + sg * 4) * 4, &g_Qh[(qrow + r) * 32 + sg * 4]);
        cpa16(sbase + (L_QL + r * QSTR + sg * 4) * 4, &g_Ql[(qrow + r) * 32 + sg * 4]);
        cpa16(sbase + (L_KH + r * QSTR + sg * 4) * 4, &g_Kh[(krow + r) * 32 + sg * 4]);
        cpa16(sbase + (L_KL + r * QSTR + sg * 4) * 4, &g_Kl[(krow + r) * 32 + sg * 4]);
    }
    cpa_commit(); cpa_wait0();
    __syncthreads();

    int lq = l & 7, lh8 = (l >> 3) & 1, lc = (l >> 4);
    int qd = l >> 3;
    unsigned aoff = ((wm * 32 + lh8 * 8 + lq) * QSTR + lc * 4) * 4;
    unsigned boff = ((wn * 64 + (qd >> 1) * 8 + lq) * QSTR + (qd & 1) * 4) * 4;

    float C[2][8][4] = {};

    #pragma unroll
    for (int ks = 0; ks < 4; ks++) {
        unsigned ah[2][4], al[2][4];
        #pragma unroll
        for (int mt = 0; mt < 2; mt++) {
            ldm4(ah[mt], sbase + L_QH * 4 + aoff + mt * (16 * QSTR * 4) + ks * 32);
            ldm4(al[mt], sbase + L_QL * 4 + aoff + mt * (16 * QSTR * 4) + ks * 32);
        }
        #pragma unroll
        for (int ntp = 0; ntp < 4; ntp++) {
            unsigned bhf[4], blf[4];
            ldm4(bhf, sbase + L_KH * 4 + boff + ntp * (16 * QSTR * 4) + ks * 32);
            ldm4(blf, sbase + L_KL * 4 + boff + ntp * (16 * QSTR * 4) + ks * 32);
            #pragma unroll
            for (int mt = 0; mt < 2; mt++) {
                mma16(C[mt][2 * ntp],     ah[mt], bhf);
                mma16(C[mt][2 * ntp],     ah[mt], blf);
                mma16(C[mt][2 * ntp],     al[mt], bhf);
                mma16(C[mt][2 * ntp + 1], ah[mt], bhf + 2);
                mma16(C[mt][2 * ntp + 1], ah[mt], blf + 2);
                mma16(C[mt][2 * ntp + 1], al[mt], bhf + 2);
            }
        }
    }

    // epilogue: exp, streaming scatter store, row sums
    float* wbase = out + OUT_OFF + (size_t)bh * S_ * S_;
    float rsum[4] = {0.f, 0.f, 0.f, 0.f};
    #pragma unroll
    for (int nt = 0; nt < 8; nt++) {
        int kk = wn * 64 + nt * 8 + 2 * tg;
        int kcol = k0 + kk;
        int jc = kk + 128;
        float mv0 = sMsk[kk];
        float mv1 = sMsk[kk + 1];
        #pragma unroll
        for (int mt = 0; mt < 2; mt++) {
            int q = q0 + wm * 32 + mt * 16 + g;
            int jq = jc - (q - q0);
            float e0 = exp_nomax(fmaf(C[mt][nt][0], 0.125f, sLut[jq]     + mv0));
            float e1 = exp_nomax(fmaf(C[mt][nt][1], 0.125f, sLut[jq + 1] + mv1));
            stg2_cs(&wbase[(size_t)q * S_ + kcol], e0, e1);
            int jq2 = jq - 8;
            float e2 = exp_nomax(fmaf(C[mt][nt][2], 0.125f, sLut[jq2]     + mv0));
            float e3 = exp_nomax(fmaf(C[mt][nt][3], 0.125f, sLut[jq2 + 1] + mv1));
            stg2_cs(&wbase[(size_t)(q + 8) * S_ + kcol], e2, e3);
            rsum[mt * 2]     += e0 + e1;
            rsum[mt * 2 + 1] += e2 + e3;
        }
    }
    #pragma unroll
    for (int ri = 0; ri < 4; ri++) {
        rsum[ri] += __shfl_xor_sync(0xffffffffu, rsum[ri], 1);
        rsum[ri] += __shfl_xor_sync(0xffffffffu, rsum[ri], 2);
    }
    __syncthreads();

    float* sSum = (float*)smu;   // [128][2]
    if (tg == 0) {
        #pragma unroll
        for (int ri = 0; ri < 4; ri++) {
            int rl = wm * 32 + (ri >> 1) * 16 + (ri & 1) * 8 + g;
            sSum[rl * 2 + wn] = rsum[ri];
        }
    }
    __syncthreads();
    if (t < 128)
        g_sums[((size_t)bh * S_ + q0 + t) * QBLK + blockIdx.x] = sSum[t * 2] + sSum[t * 2 + 1];
}

// ---------------------------------------------------------------------------
// Kernel 2: av (R10 structure). Reads expW (cp.async double-buffered), scales
// by invS, streams normalized weights out (.cs), P@V via ldmatrix + mma.
// ---------------------------------------------------------------------------
#define PSTR 36
#define RAWSTR 68
#define OFF_RAW   0
#define OFF_PH    (2 * 64 * RAWSTR)
#define OFF_PL    (OFF_PH + 64 * PSTR)
#define OFF_VH    (OFF_PL + 64 * PSTR)
#define OFF_VL    (OFF_VH + 2 * 64 * PSTR)
#define OFF_ST    (OFF_VL + 2 * 64 * PSTR)
#define AV_SMEM   ((OFF_ST + 64) * 4)

__global__ __launch_bounds__(256) void av_kernel(
    float* __restrict__ W, float* __restrict__ out)
{
    extern __shared__ unsigned smu[];
    float*    rawW = (float*)smu;
    unsigned* Ph   = smu + OFF_PH;
    unsigned* Pl   = smu + OFF_PL;
    float*    sI   = (float*)(smu + OFF_ST);

    int bh = blockIdx.y;
    int q0 = blockIdx.x * 64;

    float* Wp = W + OUT_OFF + (size_t)bh * S_ * S_;

    int t = threadIdx.x;
    int w = t >> 5, l = t & 31, g = l >> 2, tg = l & 3;
    int wm = w & 3, wn = w >> 2;

    unsigned sbase = (unsigned)__cvta_generic_to_shared(smu);

    int lq = l & 7, lh8 = (l >> 3) & 1, lc = (l >> 4);
    int qd = l >> 3;
    unsigned aoff = ((wm * 16 + lh8 * 8 + lq) * PSTR + lc * 4) * 4;
    unsigned boff = ((wn * 32 + (qd >> 1) * 8 + lq) * PSTR + (qd & 1) * 4) * 4;

    if (t < 64) {
        const float* ps = &g_sums[((size_t)bh * S_ + q0 + t) * QBLK];
        float s = 0.f;
        #pragma unroll
        for (int i = 0; i < QBLK; i++) s += ps[i];
        sI[t] = 1.0f / s;
    }

    // prefetch chunk 0 into stage 0 (V first: L2-hot, completes fast)
    {
        unsigned vb = (unsigned)bh * KBLK * 64 * 32;
        #pragma unroll
        for (int i = 0; i < 2; i++) {
            int idx = t + i * 256;
            int d = idx >> 3, sg = idx & 7;
            cpa16(sbase + (OFF_VH + d * PSTR + sg * 4) * 4, &g_Vth[vb + d * 32 + sg * 4]);
            cpa16(sbase + (OFF_VL + d * PSTR + sg * 4) * 4, &g_Vtl[vb + d * 32 + sg * 4]);
        }
        #pragma unroll
        for (int i = 0; i < 4; i++) {
            int idx = t + i * 256;
            int r = idx >> 4, c4 = idx & 15;
            cpa16(sbase + (OFF_RAW + r * RAWSTR + c4 * 4) * 4,
                  &Wp[(size_t)(q0 + r) * S_ + c4 * 4]);
        }
        cpa_commit();
    }

    float C[4][4] = {};

    for (int kci = 0; kci < KBLK; kci++) {
        int kc = kci * 64;
        int st = kci & 1;
        cpa_wait0();
        __syncthreads();

        if (kci + 1 < KBLK) {
            int s = (kci + 1) & 1;
            unsigned vb = ((unsigned)bh * KBLK + kci + 1) * 64 * 32;
            #pragma unroll
            for (int i = 0; i < 2; i++) {
                int idx = t + i * 256;
                int d = idx >> 3, sg = idx & 7;
                cpa16(sbase + (OFF_VH + s * 64 * PSTR + d * PSTR + sg * 4) * 4,
                      &g_Vth[vb + d * 32 + sg * 4]);
                cpa16(sbase + (OFF_VL + s * 64 * PSTR + d * PSTR + sg * 4) * 4,
                      &g_Vtl[vb + d * 32 + sg * 4]);
            }
            #pragma unroll
            for (int i = 0; i < 4; i++) {
                int idx = t + i * 256;
                int r = idx >> 4, c4 = idx & 15;
                cpa16(sbase + (OFF_RAW + s * 64 * RAWSTR + r * RAWSTR + c4 * 4) * 4,
                      &Wp[(size_t)(q0 + r) * S_ + kc + 64 + c4 * 4]);
            }
            cpa_commit();
        }

        // fill P: p = expW * invS; stream normalized out; pack
        #pragma unroll
        for (int i = 0; i < 4; i++) {
            int idx = t + i * 256;
            int q = idx >> 4, f4 = idx & 15;
            float4 wv = *(const float4*)&rawW[st * 64 * RAWSTR + q * RAWSTR + f4 * 4];
            float I = sI[q];
            float p0 = wv.x * I, p1 = wv.y * I, p2 = wv.z * I, p3 = wv.w * I;
            stg4_cs(&Wp[(size_t)(q0 + q) * S_ + kc + f4 * 4], make_float4(p0, p1, p2, p3));
            unsigned h0, l0, h1, l1;
            split_pack(p0, p1, h0, l0);
            split_pack(p2, p3, h1, l1);
            *(uint2*)&Ph[q * PSTR + 2 * f4] = make_uint2(h0, h1);
            *(uint2*)&Pl[q * PSTR + 2 * f4] = make_uint2(l0, l1);
        }
        __syncthreads();

        unsigned vhb = (OFF_VH + st * 64 * PSTR) * 4;
        unsigned vlb = (OFF_VL + st * 64 * PSTR) * 4;
        #pragma unroll
        for (int ks = 0; ks < 4; ks++) {
            unsigned ah[4], al[4];
            ldm4(ah, sbase + OFF_PH * 4 + aoff + ks * 32);
            ldm4(al, sbase + OFF_PL * 4 + aoff + ks * 32);
            #pragma unroll
            for (int ntp = 0; ntp < 2; ntp++) {
                unsigned bhf[4], blf[4];
                ldm4(bhf, sbase + vhb + boff + ntp * (16 * PSTR * 4) + ks * 32);
                ldm4(blf, sbase + vlb + boff + ntp * (16 * PSTR * 4) + ks * 32);
                mma16(C[2 * ntp],     ah, bhf);
                mma16(C[2 * ntp],     ah, blf);
                mma16(C[2 * ntp],     al, bhf);
                mma16(C[2 * ntp + 1], ah, bhf + 2);
                mma16(C[2 * ntp + 1], ah, blf + 2);
                mma16(C[2 * ntp + 1], al, bhf + 2);
            }
        }
        __syncthreads();
    }

    #pragma unroll
    for (int nt = 0; nt < 4; nt++) {
        int d = wn * 32 + nt * 8 + 2 * tg;
        int q = q0 + wm * 16 + g;
        *(float2*)&out[((size_t)bh * S_ + q) * D_ + d]     = make_float2(C[nt][0], C[nt][1]);
        *(float2*)&out[((size_t)bh * S_ + q + 8) * D_ + d] = make_float2(C[nt][2], C[nt][3]);
    }
}

// ---------------------------------------------------------------------------
extern "C" void kernel_launch(void* const* d_in, const int* in_sizes, int n_in,
                              void* d_out, int out_size)
{
    const float* Q    = (const float*)d_in[0];
    const float* K    = (const float*)d_in[1];
    const float* V    = (const float*)d_in[2];
    const int*   mask = (const int*)d_in[3];
    const float* bt   = (const float*)d_in[4];
    float* out = (float*)d_out;

    cudaFuncSetAttribute(logits_kernel, cudaFuncAttributeMaxDynamicSharedMemorySize, L_SMEM);
    cudaFuncSetAttribute(av_kernel,     cudaFuncAttributeMaxDynamicSharedMemorySize, AV_SMEM);

    bias_lut_kernel<<<32, 1024>>>(bt);
    qk_prep_kernel<<<BH_ * S_ * 32 / 256, 256>>>(Q, K);
    dim3 gv(KBLK, BH_);
    v_prep_kernel<<<gv, 256>>>(V);

    dim3 g1(S_ / 128, S_ / 128, BH_);   // (16, 16, 16)
    logits_kernel<<<g1, 256, L_SMEM>>>(mask, out);

    dim3 g2(S_ / 64, BH_);              // (32, 16)
    av_kernel<<<g2, 256, AV_SMEM>>>(out, out);
}

// round 15
// speedup vs baseline: 1.3178x; 1.0318x over previous
#include <cuda_runtime.h>
#include <cuda_bf16.h>
#include <cuda_fp16.h>
#include <cstdint>

#define B_ 2
#define H_ 8
#define S_ 2048
#define D_ 64
#define BH_ (B_ * H_)
#define OUT_OFF ((size_t)B_ * H_ * S_ * D_)   // output tensor first, then weights
#define KBLK 32                                // av chunks (64 wide)
#define QBLK 16                                // logits k-blocks (128 wide)

__device__ float  g_bias_lut[H_ * 2 * S_];
__device__ float  g_sums[BH_ * S_ * QBLK];    // per (row, 128-kblock) partial expsum
// packed bf16 hi/lo planes (Q, K for logits)
__device__ unsigned g_Qh[BH_ * S_ * 32];
__device__ unsigned g_Ql[BH_ * S_ * 32];
__device__ unsigned g_Kh[BH_ * S_ * 32];
__device__ unsigned g_Kl[BH_ * S_ * 32];
// packed fp16 hi/lo transposed V planes: [bh][chunk][d][kpair]
__device__ unsigned g_Vth[BH_ * KBLK * 64 * 32];
__device__ unsigned g_Vtl[BH_ * KBLK * 64 * 32];

// ---- helpers ----------------------------------------------------------------
__device__ __forceinline__ void split_pack(float x0, float x1, unsigned& hi, unsigned& lo) {
    __nv_bfloat162 h = __floats2bfloat162_rn(x0, x1);
    float f0 = __bfloat162float(__low2bfloat16(h));
    float f1 = __bfloat162float(__high2bfloat16(h));
    __nv_bfloat162 l = __floats2bfloat162_rn(x0 - f0, x1 - f1);
    hi = *reinterpret_cast<unsigned*>(&h);
    lo = *reinterpret_cast<unsigned*>(&l);
}
__device__ __forceinline__ void split_pack_h(float x0, float x1, unsigned& hi, unsigned& lo) {
    __half2 h = __floats2half2_rn(x0, x1);
    float f0 = __low2float(h), f1 = __high2float(h);
    __half2 l = __floats2half2_rn(x0 - f0, x1 - f1);
    hi = *reinterpret_cast<unsigned*>(&h);
    lo = *reinterpret_cast<unsigned*>(&l);
}
__device__ __forceinline__ void mma16(float* d, const unsigned* a, const unsigned* b) {
    asm("mma.sync.aligned.m16n8k16.row.col.f32.bf16.bf16.f32 "
        "{%0,%1,%2,%3},{%4,%5,%6,%7},{%8,%9},{%0,%1,%2,%3};"
        : "+f"(d[0]), "+f"(d[1]), "+f"(d[2]), "+f"(d[3])
        : "r"(a[0]), "r"(a[1]), "r"(a[2]), "r"(a[3]), "r"(b[0]), "r"(b[1]));
}
__device__ __forceinline__ void mma16h(float* d, const unsigned* a, const unsigned* b) {
    asm("mma.sync.aligned.m16n8k16.row.col.f32.f16.f16.f32 "
        "{%0,%1,%2,%3},{%4,%5,%6,%7},{%8,%9},{%0,%1,%2,%3};"
        : "+f"(d[0]), "+f"(d[1]), "+f"(d[2]), "+f"(d[3])
        : "r"(a[0]), "r"(a[1]), "r"(a[2]), "r"(a[3]), "r"(b[0]), "r"(b[1]));
}
__device__ __forceinline__ void ldm4(unsigned* r, unsigned addr) {
    asm volatile("ldmatrix.sync.aligned.m8n8.x4.shared.b16 {%0,%1,%2,%3}, [%4];"
        : "=r"(r[0]), "=r"(r[1]), "=r"(r[2]), "=r"(r[3]) : "r"(addr));
}
__device__ __forceinline__ void cpa16(unsigned dst, const void* src) {
    asm volatile("cp.async.cg.shared.global [%0], [%1], 16;" :: "r"(dst), "l"(src));
}
__device__ __forceinline__ void cpa_commit() { asm volatile("cp.async.commit_group;"); }
__device__ __forceinline__ void cpa_wait0()  { asm volatile("cp.async.wait_group 0;"); }
__device__ __forceinline__ float ex2f(float x) {
    float r; asm("ex2.approx.f32 %0, %1;" : "=f"(r) : "f"(x)); return r;
}
__device__ __forceinline__ void stg2_cs(float* p, float x, float y) {
    asm volatile("st.global.cs.v2.f32 [%0], {%1, %2};" :: "l"(p), "f"(x), "f"(y) : "memory");
}
__device__ __forceinline__ void stg4_cs(float* p, float4 v) {
    asm volatile("st.global.cs.v4.f32 [%0], {%1, %2, %3, %4};"
                 :: "l"(p), "f"(v.x), "f"(v.y), "f"(v.z), "f"(v.w) : "memory");
}
#define LOG2E 1.4426950408889634f
__device__ __forceinline__ float exp_nomax(float x) {
    return ex2f(fmaxf(x * LOG2E, -126.0f));
}

// ---------------------------------------------------------------------------
// Kernel 0: T5 bias LUT (exact integer bucket thresholds)
// ---------------------------------------------------------------------------
__global__ void bias_lut_kernel(const float* __restrict__ bias_table) {
    int idx = blockIdx.x * blockDim.x + threadIdx.x;
    if (idx >= H_ * 2 * S_) return;
    int h   = idx >> 12;
    int r   = idx & 4095;
    int rel = r - 2048;
    int bucket = (rel > 0) ? 16 : 0;
    int a = rel < 0 ? -rel : rel;
    int add;
    if      (a <  8) add = a;
    else if (a < 12) add = 8;
    else if (a < 16) add = 9;
    else if (a < 23) add = 10;
    else if (a < 32) add = 11;
    else if (a < 46) add = 12;
    else if (a < 64) add = 13;
    else if (a < 91) add = 14;
    else             add = 15;
    g_bias_lut[idx] = bias_table[(bucket + add) * H_ + h];
}

// ---------------------------------------------------------------------------
// Kernel 0a: Q,K -> packed row-major bf16 hi/lo planes
// ---------------------------------------------------------------------------
__global__ __launch_bounds__(256) void qk_prep_kernel(
    const float* __restrict__ Q, const float* __restrict__ K)
{
    int idx = blockIdx.x * 256 + threadIdx.x;
    const float2 q2 = *(const float2*)&Q[2 * (size_t)idx];
    const float2 k2 = *(const float2*)&K[2 * (size_t)idx];
    unsigned hi, lo;
    split_pack(q2.x, q2.y, hi, lo);
    g_Qh[idx] = hi; g_Ql[idx] = lo;
    split_pack(k2.x, k2.y, hi, lo);
    g_Kh[idx] = hi; g_Kl[idx] = lo;
}

// ---------------------------------------------------------------------------
// Kernel 0b: V -> packed transposed fp16 hi/lo planes [bh][chunk][d][kp]
// ---------------------------------------------------------------------------
__global__ __launch_bounds__(256) void v_prep_kernel(const float* __restrict__ V)
{
    __shared__ float Vs[64 * 68];
    int c  = blockIdx.x;
    int bh = blockIdx.y;
    int t  = threadIdx.x;
    const float* Vp = V + (size_t)bh * S_ * D_ + (size_t)c * 64 * D_;
    #pragma unroll
    for (int i = 0; i < 4; i++) {
        int idx = t + i * 256;
        int k = idx >> 4, d4 = idx & 15;
        *(float4*)&Vs[k * 68 + d4 * 4] = *(const float4*)&Vp[(size_t)k * D_ + d4 * 4];
    }
    __syncthreads();
    unsigned base = ((unsigned)bh * KBLK + c) * 64 * 32;
    #pragma unroll
    for (int i = 0; i < 8; i++) {
        int idx = t + i * 256;
        int d = idx >> 5, kp = idx & 31;
        unsigned hh, ll;
        split_pack_h(Vs[(2 * kp) * 68 + d], Vs[(2 * kp + 1) * 68 + d], hh, ll);
        g_Vth[base + d * 32 + kp] = hh;
        g_Vtl[base + d * 32 + kp] = ll;
    }
}

// ---------------------------------------------------------------------------
// Kernel 1: writes expW = exp(QK^T/8 + bias + mask*-1e9) + partial row sums.
// Tile 128(q) x 128(k), 8 warps (4m x 2n). bf16 3-pass. (unchanged from R14)
// ---------------------------------------------------------------------------
#define QSTR 36
#define L_QH 0
#define L_QL (128 * QSTR)
#define L_KH (2 * 128 * QSTR)
#define L_KL (3 * 128 * QSTR)
#define L_LUT (4 * 128 * QSTR)
#define L_MSK (L_LUT + 288)
#define L_SMEM ((L_MSK + 128) * 4)

__global__ __launch_bounds__(256, 2) void logits_kernel(
    const int* __restrict__ mask, float* __restrict__ out)
{
    extern __shared__ unsigned smu[];
    float* sLut = (float*)(smu + L_LUT);
    float* sMsk = (float*)(smu + L_MSK);

    int bh = blockIdx.z;
    int q0 = blockIdx.y * 128;
    int k0 = blockIdx.x * 128;
    int b  = bh >> 3;
    int h  = bh & 7;

    int t = threadIdx.x;
    int w = t >> 5, l = t & 31, g = l >> 2, tg = l & 3;
    int wm = w & 3, wn = w >> 2;

    int lbase = k0 - q0 + 2048 - 128;
    for (int i = t; i < 288; i += 256) {
        int ix = lbase + i;
        ix = ix < 0 ? 0 : (ix > 4095 ? 4095 : ix);
        sLut[i] = g_bias_lut[h * 4096 + ix];
    }
    if (t < 128)
        sMsk[t] = -1e9f * (float)mask[b * S_ + k0 + t];

    unsigned sbase = (unsigned)__cvta_generic_to_shared(smu);
    unsigned qrow = (unsigned)bh * S_ + q0;
    unsigned krow = (unsigned)bh * S_ + k0;
    #pragma unroll
    for (int i = 0; i < 4; i++) {
        int idx = t + i * 256;
        int r = idx >> 3, sg = idx & 7;
        cpa16(sbase + (L_QH + r * QSTR + sg * 4) * 4, &g_Qh[(qrow + r) * 32 + sg * 4]);
        cpa16(sbase + (L_QL + r * QSTR + sg * 4) * 4, &g_Ql[(qrow + r) * 32 + sg * 4]);
        cpa16(sbase + (L_KH + r * QSTR + sg * 4) * 4, &g_Kh[(krow + r) * 32 + sg * 4]);
        cpa16(sbase + (L_KL + r * QSTR + sg * 4) * 4, &g_Kl[(krow + r) * 32 + sg * 4]);
    }
    cpa_commit(); cpa_wait0();
    __syncthreads();

    int lq = l & 7, lh8 = (l >> 3) & 1, lc = (l >> 4);
    int qd = l >> 3;
    unsigned aoff = ((wm * 32 + lh8 * 8 + lq) * QSTR + lc * 4) * 4;
    unsigned boff = ((wn * 64 + (qd >> 1) * 8 + lq) * QSTR + (qd & 1) * 4) * 4;

    float C[2][8][4] = {};

    #pragma unroll
    for (int ks = 0; ks < 4; ks++) {
        unsigned ah[2][4], al[2][4];
        #pragma unroll
        for (int mt = 0; mt < 2; mt++) {
            ldm4(ah[mt], sbase + L_QH * 4 + aoff + mt * (16 * QSTR * 4) + ks * 32);
            ldm4(al[mt], sbase + L_QL * 4 + aoff + mt * (16 * QSTR * 4) + ks * 32);
        }
        #pragma unroll
        for (int ntp = 0; ntp < 4; ntp++) {
            unsigned bhf[4], blf[4];
            ldm4(bhf, sbase + L_KH * 4 + boff + ntp * (16 * QSTR * 4) + ks * 32);
            ldm4(blf, sbase + L_KL * 4 + boff + ntp * (16 * QSTR * 4) + ks * 32);
            #pragma unroll
            for (int mt = 0; mt < 2; mt++) {
                mma16(C[mt][2 * ntp],     ah[mt], bhf);
                mma16(C[mt][2 * ntp],     ah[mt], blf);
                mma16(C[mt][2 * ntp],     al[mt], bhf);
                mma16(C[mt][2 * ntp + 1], ah[mt], bhf + 2);
                mma16(C[mt][2 * ntp + 1], ah[mt], blf + 2);
                mma16(C[mt][2 * ntp + 1], al[mt], bhf + 2);
            }
        }
    }

    // epilogue: exp, streaming scatter store, row sums
    float* wbase = out + OUT_OFF + (size_t)bh * S_ * S_;
    float rsum[4] = {0.f, 0.f, 0.f, 0.f};
    #pragma unroll
    for (int nt = 0; nt < 8; nt++) {
        int kk = wn * 64 + nt * 8 + 2 * tg;
        int kcol = k0 + kk;
        int jc = kk + 128;
        float mv0 = sMsk[kk];
        float mv1 = sMsk[kk + 1];
        #pragma unroll
        for (int mt = 0; mt < 2; mt++) {
            int q = q0 + wm * 32 + mt * 16 + g;
            int jq = jc - (q - q0);
            float e0 = exp_nomax(fmaf(C[mt][nt][0], 0.125f, sLut[jq]     + mv0));
            float e1 = exp_nomax(fmaf(C[mt][nt][1], 0.125f, sLut[jq + 1] + mv1));
            stg2_cs(&wbase[(size_t)q * S_ + kcol], e0, e1);
            int jq2 = jq - 8;
            float e2 = exp_nomax(fmaf(C[mt][nt][2], 0.125f, sLut[jq2]     + mv0));
            float e3 = exp_nomax(fmaf(C[mt][nt][3], 0.125f, sLut[jq2 + 1] + mv1));
            stg2_cs(&wbase[(size_t)(q + 8) * S_ + kcol], e2, e3);
            rsum[mt * 2]     += e0 + e1;
            rsum[mt * 2 + 1] += e2 + e3;
        }
    }
    #pragma unroll
    for (int ri = 0; ri < 4; ri++) {
        rsum[ri] += __shfl_xor_sync(0xffffffffu, rsum[ri], 1);
        rsum[ri] += __shfl_xor_sync(0xffffffffu, rsum[ri], 2);
    }
    __syncthreads();

    float* sSum = (float*)smu;   // [128][2]
    if (tg == 0) {
        #pragma unroll
        for (int ri = 0; ri < 4; ri++) {
            int rl = wm * 32 + (ri >> 1) * 16 + (ri & 1) * 8 + g;
            sSum[rl * 2 + wn] = rsum[ri];
        }
    }
    __syncthreads();
    if (t < 128)
        g_sums[((size_t)bh * S_ + q0 + t) * QBLK + blockIdx.x] = sSum[t * 2] + sSum[t * 2 + 1];
}

// ---------------------------------------------------------------------------
// Kernel 2: av. fp16 2-pass: P as single fp16 plane (normalized, <=1),
// V as fp16 hi/lo planes. cp.async double-buffered; .cs streaming stores.
// ---------------------------------------------------------------------------
#define PSTR 36
#define RAWSTR 68
#define OFF_RAW   0
#define OFF_PH    (2 * 64 * RAWSTR)              // 8704
#define OFF_VH    (OFF_PH + 64 * PSTR)           // 11008 (2 stages)
#define OFF_VL    (OFF_VH + 2 * 64 * PSTR)       // 15616
#define OFF_ST    (OFF_VL + 2 * 64 * PSTR)       // 20224
#define AV_SMEM   ((OFF_ST + 64) * 4)            // 81152 B

__global__ __launch_bounds__(256) void av_kernel(
    float* __restrict__ W, float* __restrict__ out)
{
    extern __shared__ unsigned smu[];
    float*    rawW = (float*)smu;
    unsigned* Ph   = smu + OFF_PH;
    float*    sI   = (float*)(smu + OFF_ST);

    int bh = blockIdx.y;
    int q0 = blockIdx.x * 64;

    float* Wp = W + OUT_OFF + (size_t)bh * S_ * S_;

    int t = threadIdx.x;
    int w = t >> 5, l = t & 31, g = l >> 2, tg = l & 3;
    int wm = w & 3, wn = w >> 2;

    unsigned sbase = (unsigned)__cvta_generic_to_shared(smu);

    int lq = l & 7, lh8 = (l >> 3) & 1, lc = (l >> 4);
    int qd = l >> 3;
    unsigned aoff = ((wm * 16 + lh8 * 8 + lq) * PSTR + lc * 4) * 4;
    unsigned boff = ((wn * 32 + (qd >> 1) * 8 + lq) * PSTR + (qd & 1) * 4) * 4;

    if (t < 64) {
        const float* ps = &g_sums[((size_t)bh * S_ + q0 + t) * QBLK];
        float s = 0.f;
        #pragma unroll
        for (int i = 0; i < QBLK; i++) s += ps[i];
        sI[t] = 1.0f / s;
    }

    // prefetch chunk 0 into stage 0 (V first: L2-hot)
    {
        unsigned vb = (unsigned)bh * KBLK * 64 * 32;
        #pragma unroll
        for (int i = 0; i < 2; i++) {
            int idx = t + i * 256;
            int d = idx >> 3, sg = idx & 7;
            cpa16(sbase + (OFF_VH + d * PSTR + sg * 4) * 4, &g_Vth[vb + d * 32 + sg * 4]);
            cpa16(sbase + (OFF_VL + d * PSTR + sg * 4) * 4, &g_Vtl[vb + d * 32 + sg * 4]);
        }
        #pragma unroll
        for (int i = 0; i < 4; i++) {
            int idx = t + i * 256;
            int r = idx >> 4, c4 = idx & 15;
            cpa16(sbase + (OFF_RAW + r * RAWSTR + c4 * 4) * 4,
                  &Wp[(size_t)(q0 + r) * S_ + c4 * 4]);
        }
        cpa_commit();
    }

    float C[4][4] = {};

    for (int kci = 0; kci < KBLK; kci++) {
        int kc = kci * 64;
        int st = kci & 1;
        cpa_wait0();
        __syncthreads();

        if (kci + 1 < KBLK) {
            int s = (kci + 1) & 1;
            unsigned vb = ((unsigned)bh * KBLK + kci + 1) * 64 * 32;
            #pragma unroll
            for (int i = 0; i < 2; i++) {
                int idx = t + i * 256;
                int d = idx >> 3, sg = idx & 7;
                cpa16(sbase + (OFF_VH + s * 64 * PSTR + d * PSTR + sg * 4) * 4,
                      &g_Vth[vb + d * 32 + sg * 4]);
                cpa16(sbase + (OFF_VL + s * 64 * PSTR + d * PSTR + sg * 4) * 4,
                      &g_Vtl[vb + d * 32 + sg * 4]);
            }
            #pragma unroll
            for (int i = 0; i < 4; i++) {
                int idx = t + i * 256;
                int r = idx >> 4, c4 = idx & 15;
                cpa16(sbase + (OFF_RAW + s * 64 * RAWSTR + r * RAWSTR + c4 * 4) * 4,
                      &Wp[(size_t)(q0 + r) * S_ + kc + 64 + c4 * 4]);
            }
            cpa_commit();
        }

        // fill P: p = expW * invS (normalized, <=1); stream out; pack fp16
        #pragma unroll
        for (int i = 0; i < 4; i++) {
            int idx = t + i * 256;
            int q = idx >> 4, f4 = idx & 15;
            float4 wv = *(const float4*)&rawW[st * 64 * RAWSTR + q * RAWSTR + f4 * 4];
            float I = sI[q];
            float p0 = wv.x * I, p1 = wv.y * I, p2 = wv.z * I, p3 = wv.w * I;
            stg4_cs(&Wp[(size_t)(q0 + q) * S_ + kc + f4 * 4], make_float4(p0, p1, p2, p3));
            __half2 h0 = __floats2half2_rn(p0, p1);
            __half2 h1 = __floats2half2_rn(p2, p3);
            *(uint2*)&Ph[q * PSTR + 2 * f4] =
                make_uint2(*reinterpret_cast<unsigned*>(&h0), *reinterpret_cast<unsigned*>(&h1));
        }
        __syncthreads();

        unsigned vhb = (OFF_VH + st * 64 * PSTR) * 4;
        unsigned vlb = (OFF_VL + st * 64 * PSTR) * 4;
        #pragma unroll
        for (int ks = 0; ks < 4; ks++) {
            unsigned ah[4];
            ldm4(ah, sbase + OFF_PH * 4 + aoff + ks * 32);
            #pragma unroll
            for (int ntp = 0; ntp < 2; ntp++) {
                unsigned bhf[4], blf[4];
                ldm4(bhf, sbase + vhb + boff + ntp * (16 * PSTR * 4) + ks * 32);
                ldm4(blf, sbase + vlb + boff + ntp * (16 * PSTR * 4) + ks * 32);
                mma16h(C[2 * ntp],     ah, bhf);
                mma16h(C[2 * ntp],     ah, blf);
                mma16h(C[2 * ntp + 1], ah, bhf + 2);
                mma16h(C[2 * ntp + 1], ah, blf + 2);
            }
        }
        __syncthreads();
    }

    #pragma unroll
    for (int nt = 0; nt < 4; nt++) {
        int d = wn * 32 + nt * 8 + 2 * tg;
        int q = q0 + wm * 16 + g;
        *(float2*)&out[((size_t)bh * S_ + q) * D_ + d]     = make_float2(C[nt][0], C[nt][1]);
        *(float2*)&out[((size_t)bh * S_ + q + 8) * D_ + d] = make_float2(C[nt][2], C[nt][3]);
    }
}

// ---------------------------------------------------------------------------
extern "C" void kernel_launch(void* const* d_in, const int* in_sizes, int n_in,
                              void* d_out, int out_size)
{
    const float* Q    = (const float*)d_in[0];
    const float* K    = (const float*)d_in[1];
    const float* V    = (const float*)d_in[2];
    const int*   mask = (const int*)d_in[3];
    const float* bt   = (const float*)d_in[4];
    float* out = (float*)d_out;

    cudaFuncSetAttribute(logits_kernel, cudaFuncAttributeMaxDynamicSharedMemorySize, L_SMEM);
    cudaFuncSetAttribute(av_kernel,     cudaFuncAttributeMaxDynamicSharedMemorySize, AV_SMEM);

    bias_lut_kernel<<<32, 1024>>>(bt);
    qk_prep_kernel<<<BH_ * S_ * 32 / 256, 256>>>(Q, K);
    dim3 gv(KBLK, BH_);
    v_prep_kernel<<<gv, 256>>>(V);

    dim3 g1(S_ / 128, S_ / 128, BH_);   // (16, 16, 16)
    logits_kernel<<<g1, 256, L_SMEM>>>(mask, out);

    dim3 g2(S_ / 64, BH_);              // (32, 16)
    av_kernel<<<g2, 256, AV_SMEM>>>(out, out);
}

// round 17
// speedup vs baseline: 1.3235x; 1.0044x over previous
#include <cuda_runtime.h>
#include <cuda_bf16.h>
#include <cuda_fp16.h>
#include <cstdint>

#define B_ 2
#define H_ 8
#define S_ 2048
#define D_ 64
#define BH_ (B_ * H_)
#define OUT_OFF ((size_t)B_ * H_ * S_ * D_)   // output tensor first, then weights
#define KBLK 32                                // av chunks (64 wide)
#define QBLK 16                                // logits k-blocks (128 wide)

__device__ float  g_bias_lut[H_ * 2 * S_];
__device__ float  g_sums[BH_ * S_ * QBLK];    // per (row, 128-kblock) partial expsum
// packed bf16 hi/lo planes (Q, K for logits)
__device__ unsigned g_Qh[BH_ * S_ * 32];
__device__ unsigned g_Ql[BH_ * S_ * 32];
__device__ unsigned g_Kh[BH_ * S_ * 32];
__device__ unsigned g_Kl[BH_ * S_ * 32];
// packed fp16 hi/lo transposed V planes: [bh][chunk][d][kpair]
__device__ unsigned g_Vth[BH_ * KBLK * 64 * 32];
__device__ unsigned g_Vtl[BH_ * KBLK * 64 * 32];

// ---- helpers ----------------------------------------------------------------
__device__ __forceinline__ void split_pack(float x0, float x1, unsigned& hi, unsigned& lo) {
    __nv_bfloat162 h = __floats2bfloat162_rn(x0, x1);
    float f0 = __bfloat162float(__low2bfloat16(h));
    float f1 = __bfloat162float(__high2bfloat16(h));
    __nv_bfloat162 l = __floats2bfloat162_rn(x0 - f0, x1 - f1);
    hi = *reinterpret_cast<unsigned*>(&h);
    lo = *reinterpret_cast<unsigned*>(&l);
}
__device__ __forceinline__ void split_pack_h(float x0, float x1, unsigned& hi, unsigned& lo) {
    __half2 h = __floats2half2_rn(x0, x1);
    float f0 = __low2float(h), f1 = __high2float(h);
    __half2 l = __floats2half2_rn(x0 - f0, x1 - f1);
    hi = *reinterpret_cast<unsigned*>(&h);
    lo = *reinterpret_cast<unsigned*>(&l);
}
__device__ __forceinline__ void mma16(float* d, const unsigned* a, const unsigned* b) {
    asm("mma.sync.aligned.m16n8k16.row.col.f32.bf16.bf16.f32 "
        "{%0,%1,%2,%3},{%4,%5,%6,%7},{%8,%9},{%0,%1,%2,%3};"
        : "+f"(d[0]), "+f"(d[1]), "+f"(d[2]), "+f"(d[3])
        : "r"(a[0]), "r"(a[1]), "r"(a[2]), "r"(a[3]), "r"(b[0]), "r"(b[1]));
}
__device__ __forceinline__ void mma16h(float* d, const unsigned* a, const unsigned* b) {
    asm("mma.sync.aligned.m16n8k16.row.col.f32.f16.f16.f32 "
        "{%0,%1,%2,%3},{%4,%5,%6,%7},{%8,%9},{%0,%1,%2,%3};"
        : "+f"(d[0]), "+f"(d[1]), "+f"(d[2]), "+f"(d[3])
        : "r"(a[0]), "r"(a[1]), "r"(a[2]), "r"(a[3]), "r"(b[0]), "r"(b[1]));
}
__device__ __forceinline__ void ldm4(unsigned* r, unsigned addr) {
    asm volatile("ldmatrix.sync.aligned.m8n8.x4.shared.b16 {%0,%1,%2,%3}, [%4];"
        : "=r"(r[0]), "=r"(r[1]), "=r"(r[2]), "=r"(r[3]) : "r"(addr));
}
__device__ __forceinline__ void cpa16(unsigned dst, const void* src) {
    asm volatile("cp.async.cg.shared.global [%0], [%1], 16;" :: "r"(dst), "l"(src));
}
__device__ __forceinline__ void cpa_commit() { asm volatile("cp.async.commit_group;"); }
__device__ __forceinline__ void cpa_wait0()  { asm volatile("cp.async.wait_group 0;"); }
__device__ __forceinline__ float ex2f(float x) {
    float r; asm("ex2.approx.f32 %0, %1;" : "=f"(r) : "f"(x)); return r;
}
__device__ __forceinline__ void stg2_cs(float* p, float x, float y) {
    asm volatile("st.global.cs.v2.f32 [%0], {%1, %2};" :: "l"(p), "f"(x), "f"(y) : "memory");
}
__device__ __forceinline__ void stg4_cs(float* p, float4 v) {
    asm volatile("st.global.cs.v4.f32 [%0], {%1, %2, %3, %4};"
                 :: "l"(p), "f"(v.x), "f"(v.y), "f"(v.z), "f"(v.w) : "memory");
}
#define LOG2E 1.4426950408889634f
__device__ __forceinline__ float exp_nomax(float x) {
    return ex2f(fmaxf(x * LOG2E, -126.0f));
}

// ---------------------------------------------------------------------------
// Kernel 0: T5 bias LUT (exact integer bucket thresholds)
// ---------------------------------------------------------------------------
__global__ void bias_lut_kernel(const float* __restrict__ bias_table) {
    int idx = blockIdx.x * blockDim.x + threadIdx.x;
    if (idx >= H_ * 2 * S_) return;
    int h   = idx >> 12;
    int r   = idx & 4095;
    int rel = r - 2048;
    int bucket = (rel > 0) ? 16 : 0;
    int a = rel < 0 ? -rel : rel;
    int add;
    if      (a <  8) add = a;
    else if (a < 12) add = 8;
    else if (a < 16) add = 9;
    else if (a < 23) add = 10;
    else if (a < 32) add = 11;
    else if (a < 46) add = 12;
    else if (a < 64) add = 13;
    else if (a < 91) add = 14;
    else             add = 15;
    g_bias_lut[idx] = bias_table[(bucket + add) * H_ + h];
}

// ---------------------------------------------------------------------------
// Kernel 0a: Q,K -> packed row-major bf16 hi/lo planes
// ---------------------------------------------------------------------------
__global__ __launch_bounds__(256) void qk_prep_kernel(
    const float* __restrict__ Q, const float* __restrict__ K)
{
    int idx = blockIdx.x * 256 + threadIdx.x;
    const float2 q2 = *(const float2*)&Q[2 * (size_t)idx];
    const float2 k2 = *(const float2*)&K[2 * (size_t)idx];
    unsigned hi, lo;
    split_pack(q2.x, q2.y, hi, lo);
    g_Qh[idx] = hi; g_Ql[idx] = lo;
    split_pack(k2.x, k2.y, hi, lo);
    g_Kh[idx] = hi; g_Kl[idx] = lo;
}

// ---------------------------------------------------------------------------
// Kernel 0b: V -> packed transposed fp16 hi/lo planes [bh][chunk][d][kp]
// ---------------------------------------------------------------------------
__global__ __launch_bounds__(256) void v_prep_kernel(const float* __restrict__ V)
{
    __shared__ float Vs[64 * 68];
    int c  = blockIdx.x;
    int bh = blockIdx.y;
    int t  = threadIdx.x;
    const float* Vp = V + (size_t)bh * S_ * D_ + (size_t)c * 64 * D_;
    #pragma unroll
    for (int i = 0; i < 4; i++) {
        int idx = t + i * 256;
        int k = idx >> 4, d4 = idx & 15;
        *(float4*)&Vs[k * 68 + d4 * 4] = *(const float4*)&Vp[(size_t)k * D_ + d4 * 4];
    }
    __syncthreads();
    unsigned base = ((unsigned)bh * KBLK + c) * 64 * 32;
    #pragma unroll
    for (int i = 0; i < 8; i++) {
        int idx = t + i * 256;
        int d = idx >> 5, kp = idx & 31;
        unsigned hh, ll;
        split_pack_h(Vs[(2 * kp) * 68 + d], Vs[(2 * kp + 1) * 68 + d], hh, ll);
        g_Vth[base + d * 32 + kp] = hh;
        g_Vtl[base + d * 32 + kp] = ll;
    }
}

// ---------------------------------------------------------------------------
// Kernel 1: writes expW = exp(QK^T/8 + bias + mask*-1e9) + partial row sums.
// Tile 128(q) x 128(k), 8 warps (4m x 2n). bf16 3-pass, term-major mma order
// (dependency distance 4 instead of 1).
// ---------------------------------------------------------------------------
#define QSTR 36
#define L_QH 0
#define L_QL (128 * QSTR)
#define L_KH (2 * 128 * QSTR)
#define L_KL (3 * 128 * QSTR)
#define L_LUT (4 * 128 * QSTR)
#define L_MSK (L_LUT + 288)
#define L_SMEM ((L_MSK + 128) * 4)

__global__ __launch_bounds__(256, 2) void logits_kernel(
    const int* __restrict__ mask, float* __restrict__ out)
{
    extern __shared__ unsigned smu[];
    float* sLut = (float*)(smu + L_LUT);
    float* sMsk = (float*)(smu + L_MSK);

    int bh = blockIdx.z;
    int q0 = blockIdx.y * 128;
    int k0 = blockIdx.x * 128;
    int b  = bh >> 3;
    int h  = bh & 7;

    int t = threadIdx.x;
    int w = t >> 5, l = t & 31, g = l >> 2, tg = l & 3;
    int wm = w & 3, wn = w >> 2;

    int lbase = k0 - q0 + 2048 - 128;
    for (int i = t; i < 288; i += 256) {
        int ix = lbase + i;
        ix = ix < 0 ? 0 : (ix > 4095 ? 4095 : ix);
        sLut[i] = g_bias_lut[h * 4096 + ix];
    }
    if (t < 128)
        sMsk[t] = -1e9f * (float)mask[b * S_ + k0 + t];

    unsigned sbase = (unsigned)__cvta_generic_to_shared(smu);
    unsigned qrow = (unsigned)bh * S_ + q0;
    unsigned krow = (unsigned)bh * S_ + k0;
    #pragma unroll
    for (int i = 0; i < 4; i++) {
        int idx = t + i * 256;
        int r = idx >> 3, sg = idx & 7;
        cpa16(sbase + (L_QH + r * QSTR + sg * 4) * 4, &g_Qh[(qrow + r) * 32 + sg * 4]);
        cpa16(sbase + (L_QL + r * QSTR + sg * 4) * 4, &g_Ql[(qrow + r) * 32 + sg * 4]);
        cpa16(sbase + (L_KH + r * QSTR + sg * 4) * 4, &g_Kh[(krow + r) * 32 + sg * 4]);
        cpa16(sbase + (L_KL + r * QSTR + sg * 4) * 4, &g_Kl[(krow + r) * 32 + sg * 4]);
    }
    cpa_commit(); cpa_wait0();
    __syncthreads();

    int lq = l & 7, lh8 = (l >> 3) & 1, lc = (l >> 4);
    int qd = l >> 3;
    unsigned aoff = ((wm * 32 + lh8 * 8 + lq) * QSTR + lc * 4) * 4;
    unsigned boff = ((wn * 64 + (qd >> 1) * 8 + lq) * QSTR + (qd & 1) * 4) * 4;

    float C[2][8][4] = {};

    #pragma unroll
    for (int ks = 0; ks < 4; ks++) {
        unsigned ah[2][4], al[2][4];
        #pragma unroll
        for (int mt = 0; mt < 2; mt++) {
            ldm4(ah[mt], sbase + L_QH * 4 + aoff + mt * (16 * QSTR * 4) + ks * 32);
            ldm4(al[mt], sbase + L_QL * 4 + aoff + mt * (16 * QSTR * 4) + ks * 32);
        }
        #pragma unroll
        for (int ntp = 0; ntp < 4; ntp++) {
            unsigned bhf[4], blf[4];
            ldm4(bhf, sbase + L_KH * 4 + boff + ntp * (16 * QSTR * 4) + ks * 32);
            ldm4(blf, sbase + L_KL * 4 + boff + ntp * (16 * QSTR * 4) + ks * 32);
            // term-major: 4 independent accumulators per term
            #pragma unroll
            for (int mt = 0; mt < 2; mt++) {
                mma16(C[mt][2 * ntp],     ah[mt], bhf);
                mma16(C[mt][2 * ntp + 1], ah[mt], bhf + 2);
            }
            #pragma unroll
            for (int mt = 0; mt < 2; mt++) {
                mma16(C[mt][2 * ntp],     ah[mt], blf);
                mma16(C[mt][2 * ntp + 1], ah[mt], blf + 2);
            }
            #pragma unroll
            for (int mt = 0; mt < 2; mt++) {
                mma16(C[mt][2 * ntp],     al[mt], bhf);
                mma16(C[mt][2 * ntp + 1], al[mt], bhf + 2);
            }
        }
    }

    // epilogue: exp, streaming scatter store, row sums
    float* wbase = out + OUT_OFF + (size_t)bh * S_ * S_;
    float rsum[4] = {0.f, 0.f, 0.f, 0.f};
    #pragma unroll
    for (int nt = 0; nt < 8; nt++) {
        int kk = wn * 64 + nt * 8 + 2 * tg;
        int kcol = k0 + kk;
        int jc = kk + 128;
        float mv0 = sMsk[kk];
        float mv1 = sMsk[kk + 1];
        #pragma unroll
        for (int mt = 0; mt < 2; mt++) {
            int q = q0 + wm * 32 + mt * 16 + g;
            int jq = jc - (q - q0);
            float e0 = exp_nomax(fmaf(C[mt][nt][0], 0.125f, sLut[jq]     + mv0));
            float e1 = exp_nomax(fmaf(C[mt][nt][1], 0.125f, sLut[jq + 1] + mv1));
            stg2_cs(&wbase[(size_t)q * S_ + kcol], e0, e1);
            int jq2 = jq - 8;
            float e2 = exp_nomax(fmaf(C[mt][nt][2], 0.125f, sLut[jq2]     + mv0));
            float e3 = exp_nomax(fmaf(C[mt][nt][3], 0.125f, sLut[jq2 + 1] + mv1));
            stg2_cs(&wbase[(size_t)(q + 8) * S_ + kcol], e2, e3);
            rsum[mt * 2]     += e0 + e1;
            rsum[mt * 2 + 1] += e2 + e3;
        }
    }
    #pragma unroll
    for (int ri = 0; ri < 4; ri++) {
        rsum[ri] += __shfl_xor_sync(0xffffffffu, rsum[ri], 1);
        rsum[ri] += __shfl_xor_sync(0xffffffffu, rsum[ri], 2);
    }
    __syncthreads();

    float* sSum = (float*)smu;   // [128][2]
    if (tg == 0) {
        #pragma unroll
        for (int ri = 0; ri < 4; ri++) {
            int rl = wm * 32 + (ri >> 1) * 16 + (ri & 1) * 8 + g;
            sSum[rl * 2 + wn] = rsum[ri];
        }
    }
    __syncthreads();
    if (t < 128)
        g_sums[((size_t)bh * S_ + q0 + t) * QBLK + blockIdx.x] = sSum[t * 2] + sSum[t * 2 + 1];
}

// ---------------------------------------------------------------------------
// Kernel 2: av. fp16 2-pass, term-major mma order (distance 4). cp.async
// double-buffered; .cs streaming stores.
// ---------------------------------------------------------------------------
#define PSTR 36
#define RAWSTR 68
#define OFF_RAW   0
#define OFF_PH    (2 * 64 * RAWSTR)              // 8704
#define OFF_VH    (OFF_PH + 64 * PSTR)           // 11008 (2 stages)
#define OFF_VL    (OFF_VH + 2 * 64 * PSTR)       // 15616
#define OFF_ST    (OFF_VL + 2 * 64 * PSTR)       // 20224
#define AV_SMEM   ((OFF_ST + 64) * 4)            // 81152 B

__global__ __launch_bounds__(256) void av_kernel(
    float* __restrict__ W, float* __restrict__ out)
{
    extern __shared__ unsigned smu[];
    float*    rawW = (float*)smu;
    unsigned* Ph   = smu + OFF_PH;
    float*    sI   = (float*)(smu + OFF_ST);

    int bh = blockIdx.y;
    int q0 = blockIdx.x * 64;

    float* Wp = W + OUT_OFF + (size_t)bh * S_ * S_;

    int t = threadIdx.x;
    int w = t >> 5, l = t & 31, g = l >> 2, tg = l & 3;
    int wm = w & 3, wn = w >> 2;

    unsigned sbase = (unsigned)__cvta_generic_to_shared(smu);

    int lq = l & 7, lh8 = (l >> 3) & 1, lc = (l >> 4);
    int qd = l >> 3;
    unsigned aoff = ((wm * 16 + lh8 * 8 + lq) * PSTR + lc * 4) * 4;
    unsigned boff = ((wn * 32 + (qd >> 1) * 8 + lq) * PSTR + (qd & 1) * 4) * 4;

    if (t < 64) {
        const float* ps = &g_sums[((size_t)bh * S_ + q0 + t) * QBLK];
        float s = 0.f;
        #pragma unroll
        for (int i = 0; i < QBLK; i++) s += ps[i];
        sI[t] = 1.0f / s;
    }

    // prefetch chunk 0 into stage 0 (V first: L2-hot)
    {
        unsigned vb = (unsigned)bh * KBLK * 64 * 32;
        #pragma unroll
        for (int i = 0; i < 2; i++) {
            int idx = t + i * 256;
            int d = idx >> 3, sg = idx & 7;
            cpa16(sbase + (OFF_VH + d * PSTR + sg * 4) * 4, &g_Vth[vb + d * 32 + sg * 4]);
            cpa16(sbase + (OFF_VL + d * PSTR + sg * 4) * 4, &g_Vtl[vb + d * 32 + sg * 4]);
        }
        #pragma unroll
        for (int i = 0; i < 4; i++) {
            int idx = t + i * 256;
            int r = idx >> 4, c4 = idx & 15;
            cpa16(sbase + (OFF_RAW + r * RAWSTR + c4 * 4) * 4,
                  &Wp[(size_t)(q0 + r) * S_ + c4 * 4]);
        }
        cpa_commit();
    }

    float C[4][4] = {};

    for (int kci = 0; kci < KBLK; kci++) {
        int kc = kci * 64;
        int st = kci & 1;
        cpa_wait0();
        __syncthreads();

        if (kci + 1 < KBLK) {
            int s = (kci + 1) & 1;
            unsigned vb = ((unsigned)bh * KBLK + kci + 1) * 64 * 32;
            #pragma unroll
            for (int i = 0; i < 2; i++) {
                int idx = t + i * 256;
                int d = idx >> 3, sg = idx & 7;
                cpa16(sbase + (OFF_VH + s * 64 * PSTR + d * PSTR + sg * 4) * 4,
                      &g_Vth[vb + d * 32 + sg * 4]);
                cpa16(sbase + (OFF_VL + s * 64 * PSTR + d * PSTR + sg * 4) * 4,
                      &g_Vtl[vb + d * 32 + sg * 4]);
            }
            #pragma unroll
            for (int i = 0; i < 4; i++) {
                int idx = t + i * 256;
                int r = idx >> 4, c4 = idx & 15;
                cpa16(sbase + (OFF_RAW + s * 64 * RAWSTR + r * RAWSTR + c4 * 4) * 4,
                      &Wp[(size_t)(q0 + r) * S_ + kc + 64 + c4 * 4]);
            }
            cpa_commit();
        }

        // fill P: p = expW * invS (normalized, <=1); stream out; pack fp16
        #pragma unroll
        for (int i = 0; i < 4; i++) {
            int idx = t + i * 256;
            int q = idx >> 4, f4 = idx & 15;
            float4 wv = *(const float4*)&rawW[st * 64 * RAWSTR + q * RAWSTR + f4 * 4];
            float I = sI[q];
            float p0 = wv.x * I, p1 = wv.y * I, p2 = wv.z * I, p3 = wv.w * I;
            stg4_cs(&Wp[(size_t)(q0 + q) * S_ + kc + f4 * 4], make_float4(p0, p1, p2, p3));
            __half2 h0 = __floats2half2_rn(p0, p1);
            __half2 h1 = __floats2half2_rn(p2, p3);
            *(uint2*)&Ph[q * PSTR + 2 * f4] =
                make_uint2(*reinterpret_cast<unsigned*>(&h0), *reinterpret_cast<unsigned*>(&h1));
        }
        __syncthreads();

        unsigned vhb = (OFF_VH + st * 64 * PSTR) * 4;
        unsigned vlb = (OFF_VL + st * 64 * PSTR) * 4;
        #pragma unroll
        for (int ks = 0; ks < 4; ks++) {
            unsigned ah[4];
            ldm4(ah, sbase + OFF_PH * 4 + aoff + ks * 32);
            unsigned bhf0[4], blf0[4], bhf1[4], blf1[4];
            ldm4(bhf0, sbase + vhb + boff + ks * 32);
            ldm4(blf0, sbase + vlb + boff + ks * 32);
            ldm4(bhf1, sbase + vhb + boff + (16 * PSTR * 4) + ks * 32);
            ldm4(blf1, sbase + vlb + boff + (16 * PSTR * 4) + ks * 32);
            // term-major: all 4 accumulators hi, then all 4 lo
            mma16h(C[0], ah, bhf0);
            mma16h(C[1], ah, bhf0 + 2);
            mma16h(C[2], ah, bhf1);
            mma16h(C[3], ah, bhf1 + 2);
            mma16h(C[0], ah, blf0);
            mma16h(C[1], ah, blf0 + 2);
            mma16h(C[2], ah, blf1);
            mma16h(C[3], ah, blf1 + 2);
        }
        __syncthreads();
    }

    #pragma unroll
    for (int nt = 0; nt < 4; nt++) {
        int d = wn * 32 + nt * 8 + 2 * tg;
        int q = q0 + wm * 16 + g;
        *(float2*)&out[((size_t)bh * S_ + q) * D_ + d]     = make_float2(C[nt][0], C[nt][1]);
        *(float2*)&out[((size_t)bh * S_ + q + 8) * D_ + d] = make_float2(C[nt][2], C[nt][3]);
    }
}

// ---------------------------------------------------------------------------
extern "C" void kernel_launch(void* const* d_in, const int* in_sizes, int n_in,
                              void* d_out, int out_size)
{
    const float* Q    = (const float*)d_in[0];
    const float* K    = (const float*)d_in[1];
    const float* V    = (const float*)d_in[2];
    const int*   mask = (const int*)d_in[3];
    const float* bt   = (const float*)d_in[4];
    float* out = (float*)d_out;

    cudaFuncSetAttribute(logits_kernel, cudaFuncAttributeMaxDynamicSharedMemorySize, L_SMEM);
    cudaFuncSetAttribute(av_kernel,     cudaFuncAttributeMaxDynamicSharedMemorySize, AV_SMEM);

    bias_lut_kernel<<<32, 1024>>>(bt);
    qk_prep_kernel<<<BH_ * S_ * 32 / 256, 256>>>(Q, K);
    dim3 gv(KBLK, BH_);
    v_prep_kernel<<<gv, 256>>>(V);

    dim3 g1(S_ / 128, S_ / 128, BH_);   // (16, 16, 16)
    logits_kernel<<<g1, 256, L_SMEM>>>(mask, out);

    dim3 g2(S_ / 64, BH_);              // (32, 16)
    av_kernel<<<g2, 256, AV_SMEM>>>(out, out);
}